// round 11
// baseline (speedup 1.0000x reference)
#include <cuda_runtime.h>
#include <math.h>

#define TPB 288
#define SMEM_FLOATS 27328
#define SMEM_BYTES (SMEM_FLOATS * 4)   // 109312 B -> 2 CTAs/SM

typedef unsigned long long ull;

__device__ __forceinline__ float gelu_exact(float x) {
    return 0.5f * x * (1.0f + erff(x * 0.70710678118654752440f));
}

__device__ __forceinline__ ull mul2(ull a, ull b) {
    ull d; asm("mul.rn.f32x2 %0, %1, %2;" : "=l"(d) : "l"(a), "l"(b)); return d;
}
__device__ __forceinline__ ull fma2(ull a, ull b, ull c) {
    ull d; asm("fma.rn.f32x2 %0, %1, %2, %3;" : "=l"(d) : "l"(a), "l"(b), "l"(c)); return d;
}
__device__ __forceinline__ void unpack2(ull v, float& lo, float& hi) {
    unsigned int l, h;
    asm("mov.b64 {%0, %1}, %2;" : "=r"(l), "=r"(h) : "l"(v));
    lo = __uint_as_float(l); hi = __uint_as_float(h);
}
__device__ __forceinline__ ull pack2(float x) {
    ull d; asm("mov.b64 %0, {%1, %1};" : "=l"(d) : "f"(x)); return d;
}

// cooperative transposed weight load: g[o][c] row-major -> s[c][OUT]
template<int OUT, int CIN>
__device__ __forceinline__ void load_wT(const float* __restrict__ g, float* __restrict__ s,
                                        int tid) {
    constexpr int NQ = OUT * CIN / 4;
    for (int i = tid; i < NQ; i += TPB) {
        float4 v = ((const float4*)g)[i];
        int o = i / (CIN / 4);
        int c = (i - o * (CIN / 4)) * 4;
        s[(c + 0) * OUT + o] = v.x;
        s[(c + 1) * OUT + o] = v.y;
        s[(c + 2) * OUT + o] = v.z;
        s[(c + 3) * OUT + o] = v.w;
    }
}

// 4-output x 4-n register tile; weights transposed [c][OUT]; c ascending (R2 numerics)
// Scalar FFMA: 16 independent accumulator chains -> best ILP for latency-bound phases.
template<int CIN, int OUT>
__device__ __forceinline__ void gemm4x4T(const float* __restrict__ Wt,
                                         const float* __restrict__ X,
                                         int o0, int n0, float4 a[4]) {
    a[0] = make_float4(0.f, 0.f, 0.f, 0.f);
    a[1] = a[0]; a[2] = a[0]; a[3] = a[0];
    #pragma unroll 8
    for (int c = 0; c < CIN; c++) {
        float4 w = *(const float4*)&Wt[c * OUT + o0];
        float4 v = *(const float4*)&X[c * 144 + n0];
        a[0].x = fmaf(w.x, v.x, a[0].x); a[0].y = fmaf(w.x, v.y, a[0].y);
        a[0].z = fmaf(w.x, v.z, a[0].z); a[0].w = fmaf(w.x, v.w, a[0].w);
        a[1].x = fmaf(w.y, v.x, a[1].x); a[1].y = fmaf(w.y, v.y, a[1].y);
        a[1].z = fmaf(w.y, v.z, a[1].z); a[1].w = fmaf(w.y, v.w, a[1].w);
        a[2].x = fmaf(w.z, v.x, a[2].x); a[2].y = fmaf(w.z, v.y, a[2].y);
        a[2].z = fmaf(w.z, v.z, a[2].z); a[2].w = fmaf(w.z, v.w, a[2].w);
        a[3].x = fmaf(w.w, v.x, a[3].x); a[3].y = fmaf(w.w, v.y, a[3].y);
        a[3].z = fmaf(w.w, v.z, a[3].z); a[3].w = fmaf(w.w, v.w, a[3].w);
    }
}

__global__ void __launch_bounds__(TPB, 2) gcn_kernel(
    const float* __restrict__ gin,  const float* __restrict__ gpos, const float* __restrict__ grel,
    const float* __restrict__ gW1,  const float* __restrict__ gb1,
    const float* __restrict__ gWc,  const float* __restrict__ gbc,
    const float* __restrict__ gW2,  const float* __restrict__ gb2,
    const float* __restrict__ gF1,  const float* __restrict__ gfb1,
    const float* __restrict__ gF2,  const float* __restrict__ gfb2,
    float* __restrict__ gout)
{
    extern __shared__ float sm[];
    float* sW = sm;                   // 4096: W1T -> WcT -> [W2T | F1T | F2T]
    float* sB = sW + 4096;            // 192 biases
    float* sT = sB + 192;             // 4608: tmp = in+pos; later grapher output [c][n]
    float* sS = sT + 4608;            // 9216: stacked [2C][n]; later ffn hidden rows 0..31
    float* sU = sS + 9216;            // 9216: union { sXn/sSq/sIdx/merge | sH conv out }
    float* sXn = sU;                  // [n][c] stride 36
    float* sSq = sU + 5184;           // 144
    int*   sIdx = (int*)(sU + 5376);  // 144*9 ints -> ends at sU+5700
    float* sMrgD = sU + 5704;         // 144*9 floats (part-1 staging)
    int*   sMrgI = (int*)(sU + 7000); // 144*9 ints   -> ends at sU+8296 < 9216
    float* sH = sU;                   // conv output [64][n]

    const int tid = threadIdx.x;
    const int b   = blockIdx.x;
    const int q   = tid / 36;         // 0..7
    const int r   = tid - q * 36;     // 0..35
    const int n0  = r << 2;

    // ---------------- stage 0: W1T + biases + input(+pos) ----------------
    load_wT<32, 32>(gW1, sW, tid);
    if (tid < 32)       sB[tid] = gb1[tid];
    else if (tid < 96)  sB[tid] = gbc[tid - 32];
    else if (tid < 128) sB[tid] = gb2[tid - 96];
    else if (tid < 160) sB[tid] = gfb1[tid - 128];
    else if (tid < 192) sB[tid] = gfb2[tid - 160];
    {
        const float4* gi4 = (const float4*)(gin + (size_t)b * 4608);
        const float4* gp4 = (const float4*)gpos;
        for (int i = tid; i < 1152; i += TPB) {
            float4 a = gi4[i], p = gp4[i];
            a.x += p.x; a.y += p.y; a.z += p.z; a.w += p.w;
            ((float4*)sT)[i] = a;
        }
    }
    __syncthreads();

    // ---------------- fc1: xf = W1 @ tmp + b1 -> sS even rows ----------------
    {
        int o0 = q << 2;
        float4 a[4];
        gemm4x4T<32, 32>(sW, sT, o0, n0, a);
        #pragma unroll
        for (int j = 0; j < 4; j++) {
            float bb = sB[o0 + j];
            a[j].x += bb; a[j].y += bb; a[j].z += bb; a[j].w += bb;
            *(float4*)&sS[(2 * (o0 + j)) * 144 + n0] = a[j];
        }
    }
    __syncthreads();

    // ---------------- normalize (tid<144) in parallel with WcT load ----------------
    if (tid < 144) {
        float v[32]; float s = 0.f;
        #pragma unroll
        for (int c = 0; c < 32; c++) { float x = sS[(2 * c) * 144 + tid]; v[c] = x; s = fmaf(x, x, s); }
        float nrm = fmaxf(sqrtf(s), 1e-12f);
        float sq = 0.f;
        #pragma unroll
        for (int c = 0; c < 32; c++) { float xn = v[c] / nrm; sXn[tid * 36 + c] = xn; sq = fmaf(xn, xn, sq); }
        sSq[tid] = sq;
    } else {
        // WcT: 64x64 -> [c][64]
        constexpr int NQ = 64 * 64 / 4;
        for (int i = tid - 144; i < NQ; i += TPB - 144) {
            float4 v = ((const float4*)gWc)[i];
            int o = i / 16;
            int c = (i - o * 16) * 4;
            sW[(c + 0) * 64 + o] = v.x;
            sW[(c + 1) * 64 + o] = v.y;
            sW[(c + 2) * 64 + o] = v.z;
            sW[(c + 3) * 64 + o] = v.w;
        }
    }
    __syncthreads();

    // ---------------- pairwise dist + top-9 ----------------
    // part-major broadcast layout; m-loop unrolled x3: three independent dot streams
    // issue ahead of the (sequential, ascending-m) insert chains. Combined guard is
    // exact because bd[8] only decreases.
    {
        const int row  = (tid < 144) ? tid : tid - 144;
        const int part = (tid < 144) ? 0 : 1;
        ull vv[16];                              // all 32 channels as 16 packed pairs
        {
            const ulonglong2* xr2 = (const ulonglong2*)&sXn[row * 36];
            #pragma unroll
            for (int i = 0; i < 8; i++) { ulonglong2 t = xr2[i]; vv[2*i] = t.x; vv[2*i+1] = t.y; }
        }
        const float sqn = sSq[row];
        float bd[9]; int bi[9];
        #pragma unroll
        for (int k = 0; k < 9; k++) { bd[k] = 3.0e38f; bi[k] = 0; }
        const int m0 = part * 72;
        const float* relp = grel + (size_t)m0 * 144 + row;
        float relv0 = relp[0];
        float relv1 = relp[144];
        float relv2 = relp[288];
        relp += 432;
        for (int mm = 0; mm < 72; mm += 3) {
            const int m = m0 + mm;
            float reln0 = 0.f, reln1 = 0.f, reln2 = 0.f;
            if (mm < 69) { reln0 = relp[0]; reln1 = relp[144]; reln2 = relp[288]; }
            relp += 432;
            const ulonglong2* xa2 = (const ulonglong2*)&sXn[m * 36];
            const ulonglong2* xb2 = (const ulonglong2*)&sXn[(m + 1) * 36];
            const ulonglong2* xc2 = (const ulonglong2*)&sXn[(m + 2) * 36];
            ulonglong2 t = xa2[0];
            ull a01 = mul2(vv[0], t.x);
            ull a23 = mul2(vv[1], t.y);
            ulonglong2 u = xb2[0];
            ull b01 = mul2(vv[0], u.x);
            ull b23 = mul2(vv[1], u.y);
            ulonglong2 w = xc2[0];
            ull c01 = mul2(vv[0], w.x);
            ull c23 = mul2(vv[1], w.y);
            #pragma unroll
            for (int i = 1; i < 8; i++) {
                t = xa2[i];
                a01 = fma2(vv[2*i],   t.x, a01);
                a23 = fma2(vv[2*i+1], t.y, a23);
                u = xb2[i];
                b01 = fma2(vv[2*i],   u.x, b01);
                b23 = fma2(vv[2*i+1], u.y, b23);
                w = xc2[i];
                c01 = fma2(vv[2*i],   w.x, c01);
                c23 = fma2(vv[2*i+1], w.y, c23);
            }
            float a0, a1, a2, a3, e0, e1, e2, e3, f0, f1, f2, f3;
            unpack2(a01, a0, a1); unpack2(a23, a2, a3);
            unpack2(b01, e0, e1); unpack2(b23, e2, e3);
            unpack2(c01, f0, f1); unpack2(c23, f2, f3);
            float dota = (a0 + a1) + (a2 + a3);
            float dotb = (e0 + e1) + (e2 + e3);
            float dotc = (f0 + f1) + (f2 + f3);
            float da = (sqn - 2.0f * dota) + sSq[m]     + relv0;
            float db = (sqn - 2.0f * dotb) + sSq[m + 1] + relv1;
            float dc = (sqn - 2.0f * dotc) + sSq[m + 2] + relv2;
            relv0 = reln0; relv1 = reln1; relv2 = reln2;
            if (fminf(fminf(da, db), dc) < bd[8]) {
                // insert in ascending m order (preserves lax.top_k tie rule)
                if (da < bd[8]) {
                    bd[8] = da; bi[8] = m;
                    #pragma unroll
                    for (int j = 8; j > 0; --j) {
                        if (bd[j] < bd[j-1]) {
                            float td = bd[j]; bd[j] = bd[j-1]; bd[j-1] = td;
                            int   ti = bi[j]; bi[j] = bi[j-1]; bi[j-1] = ti;
                        }
                    }
                }
                if (db < bd[8]) {
                    bd[8] = db; bi[8] = m + 1;
                    #pragma unroll
                    for (int j = 8; j > 0; --j) {
                        if (bd[j] < bd[j-1]) {
                            float td = bd[j]; bd[j] = bd[j-1]; bd[j-1] = td;
                            int   ti = bi[j]; bi[j] = bi[j-1]; bi[j-1] = ti;
                        }
                    }
                }
                if (dc < bd[8]) {
                    bd[8] = dc; bi[8] = m + 2;
                    #pragma unroll
                    for (int j = 8; j > 0; --j) {
                        if (bd[j] < bd[j-1]) {
                            float td = bd[j]; bd[j] = bd[j-1]; bd[j-1] = td;
                            int   ti = bi[j]; bi[j] = bi[j-1]; bi[j-1] = ti;
                        }
                    }
                }
            }
        }
        if (part == 1) {                          // stage part-1 lists
            int base = row * 9;
            #pragma unroll
            for (int k = 0; k < 9; k++) { sMrgD[base + k] = bd[k]; sMrgI[base + k] = bi[k]; }
        }
        __syncthreads();
        if (part == 0) {                          // merge (ascending m preserves tie rule)
            int base = row * 9;
            #pragma unroll
            for (int k = 0; k < 9; k++) {
                float d = sMrgD[base + k]; int mi = sMrgI[base + k];
                if (d < bd[8]) {
                    bd[8] = d; bi[8] = mi;
                    #pragma unroll
                    for (int j = 8; j > 0; --j) {
                        if (bd[j] < bd[j-1]) {
                            float td = bd[j]; bd[j] = bd[j-1]; bd[j-1] = td;
                            int   ti = bi[j]; bi[j] = bi[j-1]; bi[j-1] = ti;
                        }
                    }
                }
            }
            #pragma unroll
            for (int k = 0; k < 9; k++) sIdx[row * 9 + k] = bi[k];
        }
    }
    __syncthreads();

    // ---------------- MRConv: max over gathers, then subtract (bit-identical) ----------------
    {
        const int n2 = tid % 144;
        const int g  = tid / 144;          // 0..1 -> channels g*16..g*16+15
        int idx9[9];
        #pragma unroll
        for (int k = 0; k < 9; k++) idx9[k] = sIdx[n2 * 9 + k];
        #pragma unroll
        for (int cc = 0; cc < 16; cc++) {
            int c = g * 16 + cc;
            const float* xrow = &sS[(2 * c) * 144];
            float mx = xrow[idx9[0]];
            #pragma unroll
            for (int k = 1; k < 9; k++) mx = fmaxf(mx, xrow[idx9[k]]);
            sS[(2 * c + 1) * 144 + n2] = mx - xrow[n2];
        }
    }
    __syncthreads();

    // ---------------- hoist W2/F1/F2 LDGs (stores happen after conv barrier) ----------------
    float4 wreg[4];
    {
        #pragma unroll
        for (int k = 0; k < 4; k++) {
            int i = tid + k * TPB;
            if (i < 1024) {
                if (i < 512)      wreg[k] = ((const float4*)gW2)[i];
                else if (i < 768) wreg[k] = ((const float4*)gF1)[i - 512];
                else              wreg[k] = ((const float4*)gF2)[i - 768];
            }
        }
    }

    // ---------------- conv: hc = gelu(WcT @ stacked + bc), 8o x 4n, FFMA2-packed ----------------
    {
        const int o0 = q << 3;             // 0..56
        ull A[4][4];                       // [output-pair p][n]
        #pragma unroll
        for (int p = 0; p < 4; p++)
            #pragma unroll
            for (int n = 0; n < 4; n++) A[p][n] = 0ULL;
        #pragma unroll 4
        for (int c = 0; c < 64; c++) {
            ulonglong2 wa = *(const ulonglong2*)&sW[c * 64 + o0];      // pairs (o0,o0+1),(o0+2,o0+3)
            ulonglong2 wb = *(const ulonglong2*)&sW[c * 64 + o0 + 4];  // pairs (o0+4,o0+5),(o0+6,o0+7)
            float4 v = *(const float4*)&sS[c * 144 + n0];
            ull vd0 = pack2(v.x), vd1 = pack2(v.y), vd2 = pack2(v.z), vd3 = pack2(v.w);
            A[0][0] = fma2(wa.x, vd0, A[0][0]); A[0][1] = fma2(wa.x, vd1, A[0][1]);
            A[0][2] = fma2(wa.x, vd2, A[0][2]); A[0][3] = fma2(wa.x, vd3, A[0][3]);
            A[1][0] = fma2(wa.y, vd0, A[1][0]); A[1][1] = fma2(wa.y, vd1, A[1][1]);
            A[1][2] = fma2(wa.y, vd2, A[1][2]); A[1][3] = fma2(wa.y, vd3, A[1][3]);
            A[2][0] = fma2(wb.x, vd0, A[2][0]); A[2][1] = fma2(wb.x, vd1, A[2][1]);
            A[2][2] = fma2(wb.x, vd2, A[2][2]); A[2][3] = fma2(wb.x, vd3, A[2][3]);
            A[3][0] = fma2(wb.y, vd0, A[3][0]); A[3][1] = fma2(wb.y, vd1, A[3][1]);
            A[3][2] = fma2(wb.y, vd2, A[3][2]); A[3][3] = fma2(wb.y, vd3, A[3][3]);
        }
        #pragma unroll
        for (int p = 0; p < 4; p++) {
            float4 lo4, hi4;
            unpack2(A[p][0], lo4.x, hi4.x);
            unpack2(A[p][1], lo4.y, hi4.y);
            unpack2(A[p][2], lo4.z, hi4.z);
            unpack2(A[p][3], lo4.w, hi4.w);
            float be = sB[32 + o0 + 2 * p];
            float bo = sB[32 + o0 + 2 * p + 1];
            lo4.x = gelu_exact(lo4.x + be); lo4.y = gelu_exact(lo4.y + be);
            lo4.z = gelu_exact(lo4.z + be); lo4.w = gelu_exact(lo4.w + be);
            hi4.x = gelu_exact(hi4.x + bo); hi4.y = gelu_exact(hi4.y + bo);
            hi4.z = gelu_exact(hi4.z + bo); hi4.w = gelu_exact(hi4.w + bo);
            *(float4*)&sH[(o0 + 2 * p) * 144 + n0]     = lo4;
            *(float4*)&sH[(o0 + 2 * p + 1) * 144 + n0] = hi4;
        }
    }
    __syncthreads();

    // ---------------- scatter hoisted weights: [W2T | F1T | F2T] ----------------
    {
        #pragma unroll
        for (int k = 0; k < 4; k++) {
            int i = tid + k * TPB;
            if (i < 1024) {
                float4 v = wreg[k];
                if (i < 512) {                    // W2: OUT=32, CIN=64
                    int o = i / 16, c = (i - o * 16) * 4;
                    sW[(c + 0) * 32 + o] = v.x; sW[(c + 1) * 32 + o] = v.y;
                    sW[(c + 2) * 32 + o] = v.z; sW[(c + 3) * 32 + o] = v.w;
                } else if (i < 768) {             // F1: OUT=32, CIN=32
                    int j = i - 512, o = j / 8, c = (j - o * 8) * 4;
                    float* d = sW + 2048;
                    d[(c + 0) * 32 + o] = v.x; d[(c + 1) * 32 + o] = v.y;
                    d[(c + 2) * 32 + o] = v.z; d[(c + 3) * 32 + o] = v.w;
                } else {                          // F2: OUT=32, CIN=32
                    int j = i - 768, o = j / 8, c = (j - o * 8) * 4;
                    float* d = sW + 3072;
                    d[(c + 0) * 32 + o] = v.x; d[(c + 1) * 32 + o] = v.y;
                    d[(c + 2) * 32 + o] = v.z; d[(c + 3) * 32 + o] = v.w;
                }
            }
        }
    }
    __syncthreads();

    // ---------------- fc2 + residual -> sT (in place) ----------------
    {
        int o0 = q << 2;
        float4 a[4];
        gemm4x4T<64, 32>(sW, sH, o0, n0, a);
        #pragma unroll
        for (int j = 0; j < 4; j++) {
            float bb = sB[96 + o0 + j];
            float4 t = *(float4*)&sT[(o0 + j) * 144 + n0];
            a[j].x += bb + t.x; a[j].y += bb + t.y; a[j].z += bb + t.z; a[j].w += bb + t.w;
            *(float4*)&sT[(o0 + j) * 144 + n0] = a[j];
        }
    }
    __syncthreads();

    // ---------------- FFN fc1 -> sS rows 0..31 ----------------
    {
        int o0 = q << 2;
        float4 a[4];
        gemm4x4T<32, 32>(sW + 2048, sT, o0, n0, a);
        #pragma unroll
        for (int j = 0; j < 4; j++) {
            float bb = sB[128 + o0 + j];
            a[j].x = gelu_exact(a[j].x + bb); a[j].y = gelu_exact(a[j].y + bb);
            a[j].z = gelu_exact(a[j].z + bb); a[j].w = gelu_exact(a[j].w + bb);
            *(float4*)&sS[(o0 + j) * 144 + n0] = a[j];
        }
    }
    __syncthreads();

    // ---------------- FFN fc2 + residual -> global ----------------
    {
        int o0 = q << 2;
        float4 a[4];
        gemm4x4T<32, 32>(sW + 3072, sS, o0, n0, a);
        float* go = gout + (size_t)b * 4608;
        #pragma unroll
        for (int j = 0; j < 4; j++) {
            float bb = sB[160 + o0 + j];
            float4 t = *(float4*)&sT[(o0 + j) * 144 + n0];
            a[j].x += bb + t.x; a[j].y += bb + t.y; a[j].z += bb + t.z; a[j].w += bb + t.w;
            *(float4*)&go[(o0 + j) * 144 + n0] = a[j];
        }
    }
}

extern "C" void kernel_launch(void* const* d_in, const int* in_sizes, int n_in,
                              void* d_out, int out_size) {
    (void)n_in; (void)out_size;
    int B = in_sizes[0] / (32 * 144);
    cudaFuncSetAttribute(gcn_kernel, cudaFuncAttributeMaxDynamicSharedMemorySize, SMEM_BYTES);
    gcn_kernel<<<B, TPB, SMEM_BYTES>>>(
        (const float*)d_in[0],  (const float*)d_in[1],  (const float*)d_in[2],
        (const float*)d_in[3],  (const float*)d_in[4],
        (const float*)d_in[5],  (const float*)d_in[6],
        (const float*)d_in[7],  (const float*)d_in[8],
        (const float*)d_in[9],  (const float*)d_in[10],
        (const float*)d_in[11], (const float*)d_in[12],
        (float*)d_out);
}

// round 12
// speedup vs baseline: 1.0198x; 1.0198x over previous
#include <cuda_runtime.h>
#include <math.h>

#define TPB 288
#define SMEM_FLOATS 27328
#define SMEM_BYTES (SMEM_FLOATS * 4)   // 109312 B -> 2 CTAs/SM

typedef unsigned long long ull;

__device__ __forceinline__ float gelu_exact(float x) {
    return 0.5f * x * (1.0f + erff(x * 0.70710678118654752440f));
}

__device__ __forceinline__ ull mul2(ull a, ull b) {
    ull d; asm("mul.rn.f32x2 %0, %1, %2;" : "=l"(d) : "l"(a), "l"(b)); return d;
}
__device__ __forceinline__ ull fma2(ull a, ull b, ull c) {
    ull d; asm("fma.rn.f32x2 %0, %1, %2, %3;" : "=l"(d) : "l"(a), "l"(b), "l"(c)); return d;
}
__device__ __forceinline__ void unpack2(ull v, float& lo, float& hi) {
    unsigned int l, h;
    asm("mov.b64 {%0, %1}, %2;" : "=r"(l), "=r"(h) : "l"(v));
    lo = __uint_as_float(l); hi = __uint_as_float(h);
}
__device__ __forceinline__ ull pack2(float x) {
    ull d; asm("mov.b64 %0, {%1, %1};" : "=l"(d) : "f"(x)); return d;
}

// cooperative transposed weight load: g[o][c] row-major -> s[c][OUT]
template<int OUT, int CIN>
__device__ __forceinline__ void load_wT(const float* __restrict__ g, float* __restrict__ s,
                                        int tid) {
    constexpr int NQ = OUT * CIN / 4;
    for (int i = tid; i < NQ; i += TPB) {
        float4 v = ((const float4*)g)[i];
        int o = i / (CIN / 4);
        int c = (i - o * (CIN / 4)) * 4;
        s[(c + 0) * OUT + o] = v.x;
        s[(c + 1) * OUT + o] = v.y;
        s[(c + 2) * OUT + o] = v.z;
        s[(c + 3) * OUT + o] = v.w;
    }
}

// 4-output x 4-n register tile; weights transposed [c][OUT]; c ascending (R2 numerics)
// Scalar FFMA: 16 independent accumulator chains -> best ILP for latency-bound phases.
template<int CIN, int OUT>
__device__ __forceinline__ void gemm4x4T(const float* __restrict__ Wt,
                                         const float* __restrict__ X,
                                         int o0, int n0, float4 a[4]) {
    a[0] = make_float4(0.f, 0.f, 0.f, 0.f);
    a[1] = a[0]; a[2] = a[0]; a[3] = a[0];
    #pragma unroll 8
    for (int c = 0; c < CIN; c++) {
        float4 w = *(const float4*)&Wt[c * OUT + o0];
        float4 v = *(const float4*)&X[c * 144 + n0];
        a[0].x = fmaf(w.x, v.x, a[0].x); a[0].y = fmaf(w.x, v.y, a[0].y);
        a[0].z = fmaf(w.x, v.z, a[0].z); a[0].w = fmaf(w.x, v.w, a[0].w);
        a[1].x = fmaf(w.y, v.x, a[1].x); a[1].y = fmaf(w.y, v.y, a[1].y);
        a[1].z = fmaf(w.y, v.z, a[1].z); a[1].w = fmaf(w.y, v.w, a[1].w);
        a[2].x = fmaf(w.z, v.x, a[2].x); a[2].y = fmaf(w.z, v.y, a[2].y);
        a[2].z = fmaf(w.z, v.z, a[2].z); a[2].w = fmaf(w.z, v.w, a[2].w);
        a[3].x = fmaf(w.w, v.x, a[3].x); a[3].y = fmaf(w.w, v.y, a[3].y);
        a[3].z = fmaf(w.w, v.z, a[3].z); a[3].w = fmaf(w.w, v.w, a[3].w);
    }
}

__global__ void __launch_bounds__(TPB, 2) gcn_kernel(
    const float* __restrict__ gin,  const float* __restrict__ gpos, const float* __restrict__ grel,
    const float* __restrict__ gW1,  const float* __restrict__ gb1,
    const float* __restrict__ gWc,  const float* __restrict__ gbc,
    const float* __restrict__ gW2,  const float* __restrict__ gb2,
    const float* __restrict__ gF1,  const float* __restrict__ gfb1,
    const float* __restrict__ gF2,  const float* __restrict__ gfb2,
    float* __restrict__ gout)
{
    extern __shared__ float sm[];
    float* sW = sm;                   // 4096: W1T -> WcT -> [W2T | F1T | F2T]
    float* sB = sW + 4096;            // 192 biases
    float* sT = sB + 192;             // 4608: tmp = in+pos; later grapher output [c][n]
    float* sS = sT + 4608;            // 9216: stacked [2C][n]; later ffn hidden rows 0..31
    float* sU = sS + 9216;            // 9216: union { sXn/sSq/sIdx/merge | sH conv out }
    float* sXn = sU;                  // [n][c] stride 36
    float* sSq = sU + 5184;           // 144
    int*   sIdx = (int*)(sU + 5376);  // 144*9 ints -> ends at sU+5700
    float* sMrgD = sU + 5704;         // 144*9 floats (part-1 staging)
    int*   sMrgI = (int*)(sU + 7000); // 144*9 ints   -> ends at sU+8296 < 9216
    float* sH = sU;                   // conv output [64][n]

    const int tid = threadIdx.x;
    const int b   = blockIdx.x;
    const int q   = tid / 36;         // 0..7
    const int r   = tid - q * 36;     // 0..35
    const int n0  = r << 2;

    // ---------------- stage 0: W1T + biases + input(+pos) ----------------
    load_wT<32, 32>(gW1, sW, tid);
    if (tid < 32)       sB[tid] = gb1[tid];
    else if (tid < 96)  sB[tid] = gbc[tid - 32];
    else if (tid < 128) sB[tid] = gb2[tid - 96];
    else if (tid < 160) sB[tid] = gfb1[tid - 128];
    else if (tid < 192) sB[tid] = gfb2[tid - 160];
    {
        const float4* gi4 = (const float4*)(gin + (size_t)b * 4608);
        const float4* gp4 = (const float4*)gpos;
        for (int i = tid; i < 1152; i += TPB) {
            float4 a = gi4[i], p = gp4[i];
            a.x += p.x; a.y += p.y; a.z += p.z; a.w += p.w;
            ((float4*)sT)[i] = a;
        }
    }
    __syncthreads();

    // ---------------- fc1: xf = W1 @ tmp + b1 -> sS even rows ----------------
    {
        int o0 = q << 2;
        float4 a[4];
        gemm4x4T<32, 32>(sW, sT, o0, n0, a);
        #pragma unroll
        for (int j = 0; j < 4; j++) {
            float bb = sB[o0 + j];
            a[j].x += bb; a[j].y += bb; a[j].z += bb; a[j].w += bb;
            *(float4*)&sS[(2 * (o0 + j)) * 144 + n0] = a[j];
        }
    }
    __syncthreads();

    // ---------------- normalize (tid<144) in parallel with WcT load ----------------
    if (tid < 144) {
        float v[32]; float s = 0.f;
        #pragma unroll
        for (int c = 0; c < 32; c++) { float x = sS[(2 * c) * 144 + tid]; v[c] = x; s = fmaf(x, x, s); }
        float nrm = fmaxf(sqrtf(s), 1e-12f);
        float sq = 0.f;
        #pragma unroll
        for (int c = 0; c < 32; c++) { float xn = v[c] / nrm; sXn[tid * 36 + c] = xn; sq = fmaf(xn, xn, sq); }
        sSq[tid] = sq;
    } else {
        // WcT: 64x64 -> [c][64]
        constexpr int NQ = 64 * 64 / 4;
        for (int i = tid - 144; i < NQ; i += TPB - 144) {
            float4 v = ((const float4*)gWc)[i];
            int o = i / 16;
            int c = (i - o * 16) * 4;
            sW[(c + 0) * 64 + o] = v.x;
            sW[(c + 1) * 64 + o] = v.y;
            sW[(c + 2) * 64 + o] = v.z;
            sW[(c + 3) * 64 + o] = v.w;
        }
    }
    __syncthreads();

    // ---------------- pairwise dist + top-9 ----------------
    // part-major broadcast layout; m-loop unrolled x2: both dot-products issue before
    // the two (sequential, ascending-m) insert chains. rel and sq values prefetched one
    // pair ahead; xm row pointers strength-reduced.
    {
        const int row  = (tid < 144) ? tid : tid - 144;
        const int part = (tid < 144) ? 0 : 1;
        ull vv[16];                              // all 32 channels as 16 packed pairs
        {
            const ulonglong2* xr2 = (const ulonglong2*)&sXn[row * 36];
            #pragma unroll
            for (int i = 0; i < 8; i++) { ulonglong2 t = xr2[i]; vv[2*i] = t.x; vv[2*i+1] = t.y; }
        }
        const float sqn = sSq[row];
        float bd[9]; int bi[9];
        #pragma unroll
        for (int k = 0; k < 9; k++) { bd[k] = 3.0e38f; bi[k] = 0; }
        const int m0 = part * 72;
        const float* relp = grel + (size_t)m0 * 144 + row;
        const float* sqp  = sSq + m0;
        const ulonglong2* xrow2 = (const ulonglong2*)&sXn[m0 * 36];   // advance by 9 ull2 per m
        float relv0 = relp[0];
        float relv1 = relp[144];
        float sqv0  = sqp[0];
        float sqv1  = sqp[1];
        relp += 288;
        sqp  += 2;
        for (int mm = 0; mm < 72; mm += 2) {
            const int m = m0 + mm;
            float reln0 = 0.f, reln1 = 0.f, sqn0 = 0.f, sqn1 = 0.f;
            if (mm < 70) {
                reln0 = relp[0]; reln1 = relp[144];      // prefetch next pair
                sqn0  = sqp[0];  sqn1  = sqp[1];
            }
            relp += 288;
            sqp  += 2;
            const ulonglong2* xa2 = xrow2;
            const ulonglong2* xb2 = xrow2 + 9;
            xrow2 += 18;
            ulonglong2 t = xa2[0];
            ull a01 = mul2(vv[0], t.x);
            ull a23 = mul2(vv[1], t.y);
            ulonglong2 u = xb2[0];
            ull b01 = mul2(vv[0], u.x);
            ull b23 = mul2(vv[1], u.y);
            #pragma unroll
            for (int i = 1; i < 8; i++) {
                t = xa2[i];
                a01 = fma2(vv[2*i],   t.x, a01);
                a23 = fma2(vv[2*i+1], t.y, a23);
                u = xb2[i];
                b01 = fma2(vv[2*i],   u.x, b01);
                b23 = fma2(vv[2*i+1], u.y, b23);
            }
            float a0, a1, a2, a3, e0, e1, e2, e3;
            unpack2(a01, a0, a1); unpack2(a23, a2, a3);
            unpack2(b01, e0, e1); unpack2(b23, e2, e3);
            float dota = (a0 + a1) + (a2 + a3);
            float dotb = (e0 + e1) + (e2 + e3);
            float da = (sqn - 2.0f * dota) + sqv0 + relv0;
            float db = (sqn - 2.0f * dotb) + sqv1 + relv1;
            relv0 = reln0; relv1 = reln1;
            sqv0  = sqn0;  sqv1  = sqn1;
            // insert m first, then m+1 (ascending order preserves lax.top_k tie rule)
            if (da < bd[8]) {
                bd[8] = da; bi[8] = m;
                #pragma unroll
                for (int j = 8; j > 0; --j) {
                    if (bd[j] < bd[j-1]) {
                        float td = bd[j]; bd[j] = bd[j-1]; bd[j-1] = td;
                        int   ti = bi[j]; bi[j] = bi[j-1]; bi[j-1] = ti;
                    }
                }
            }
            if (db < bd[8]) {
                bd[8] = db; bi[8] = m + 1;
                #pragma unroll
                for (int j = 8; j > 0; --j) {
                    if (bd[j] < bd[j-1]) {
                        float td = bd[j]; bd[j] = bd[j-1]; bd[j-1] = td;
                        int   ti = bi[j]; bi[j] = bi[j-1]; bi[j-1] = ti;
                    }
                }
            }
        }
        if (part == 1) {                          // stage part-1 lists
            int base = row * 9;
            #pragma unroll
            for (int k = 0; k < 9; k++) { sMrgD[base + k] = bd[k]; sMrgI[base + k] = bi[k]; }
        }
        __syncthreads();
        if (part == 0) {                          // merge (ascending m preserves tie rule)
            int base = row * 9;
            #pragma unroll
            for (int k = 0; k < 9; k++) {
                float d = sMrgD[base + k]; int mi = sMrgI[base + k];
                if (d < bd[8]) {
                    bd[8] = d; bi[8] = mi;
                    #pragma unroll
                    for (int j = 8; j > 0; --j) {
                        if (bd[j] < bd[j-1]) {
                            float td = bd[j]; bd[j] = bd[j-1]; bd[j-1] = td;
                            int   ti = bi[j]; bi[j] = bi[j-1]; bi[j-1] = ti;
                        }
                    }
                }
            }
            #pragma unroll
            for (int k = 0; k < 9; k++) sIdx[row * 9 + k] = bi[k];
        }
    }
    __syncthreads();

    // ---------------- MRConv: max over gathers, then subtract (bit-identical) ----------------
    {
        const int n2 = tid % 144;
        const int g  = tid / 144;          // 0..1 -> channels g*16..g*16+15
        int idx9[9];
        #pragma unroll
        for (int k = 0; k < 9; k++) idx9[k] = sIdx[n2 * 9 + k];
        #pragma unroll
        for (int cc = 0; cc < 16; cc++) {
            int c = g * 16 + cc;
            const float* xrow = &sS[(2 * c) * 144];
            float mx = xrow[idx9[0]];
            #pragma unroll
            for (int k = 1; k < 9; k++) mx = fmaxf(mx, xrow[idx9[k]]);
            sS[(2 * c + 1) * 144 + n2] = mx - xrow[n2];
        }
    }
    __syncthreads();

    // ---------------- hoist W2/F1/F2 LDGs (stores happen after conv barrier) ----------------
    float4 wreg[4];
    {
        #pragma unroll
        for (int k = 0; k < 4; k++) {
            int i = tid + k * TPB;
            if (i < 1024) {
                if (i < 512)      wreg[k] = ((const float4*)gW2)[i];
                else if (i < 768) wreg[k] = ((const float4*)gF1)[i - 512];
                else              wreg[k] = ((const float4*)gF2)[i - 768];
            }
        }
    }

    // ---------------- conv: hc = gelu(WcT @ stacked + bc), 8o x 4n, FFMA2-packed ----------------
    {
        const int o0 = q << 3;             // 0..56
        ull A[4][4];                       // [output-pair p][n]
        #pragma unroll
        for (int p = 0; p < 4; p++)
            #pragma unroll
            for (int n = 0; n < 4; n++) A[p][n] = 0ULL;
        #pragma unroll 4
        for (int c = 0; c < 64; c++) {
            ulonglong2 wa = *(const ulonglong2*)&sW[c * 64 + o0];      // pairs (o0,o0+1),(o0+2,o0+3)
            ulonglong2 wb = *(const ulonglong2*)&sW[c * 64 + o0 + 4];  // pairs (o0+4,o0+5),(o0+6,o0+7)
            float4 v = *(const float4*)&sS[c * 144 + n0];
            ull vd0 = pack2(v.x), vd1 = pack2(v.y), vd2 = pack2(v.z), vd3 = pack2(v.w);
            A[0][0] = fma2(wa.x, vd0, A[0][0]); A[0][1] = fma2(wa.x, vd1, A[0][1]);
            A[0][2] = fma2(wa.x, vd2, A[0][2]); A[0][3] = fma2(wa.x, vd3, A[0][3]);
            A[1][0] = fma2(wa.y, vd0, A[1][0]); A[1][1] = fma2(wa.y, vd1, A[1][1]);
            A[1][2] = fma2(wa.y, vd2, A[1][2]); A[1][3] = fma2(wa.y, vd3, A[1][3]);
            A[2][0] = fma2(wb.x, vd0, A[2][0]); A[2][1] = fma2(wb.x, vd1, A[2][1]);
            A[2][2] = fma2(wb.x, vd2, A[2][2]); A[2][3] = fma2(wb.x, vd3, A[2][3]);
            A[3][0] = fma2(wb.y, vd0, A[3][0]); A[3][1] = fma2(wb.y, vd1, A[3][1]);
            A[3][2] = fma2(wb.y, vd2, A[3][2]); A[3][3] = fma2(wb.y, vd3, A[3][3]);
        }
        #pragma unroll
        for (int p = 0; p < 4; p++) {
            float4 lo4, hi4;
            unpack2(A[p][0], lo4.x, hi4.x);
            unpack2(A[p][1], lo4.y, hi4.y);
            unpack2(A[p][2], lo4.z, hi4.z);
            unpack2(A[p][3], lo4.w, hi4.w);
            float be = sB[32 + o0 + 2 * p];
            float bo = sB[32 + o0 + 2 * p + 1];
            lo4.x = gelu_exact(lo4.x + be); lo4.y = gelu_exact(lo4.y + be);
            lo4.z = gelu_exact(lo4.z + be); lo4.w = gelu_exact(lo4.w + be);
            hi4.x = gelu_exact(hi4.x + bo); hi4.y = gelu_exact(hi4.y + bo);
            hi4.z = gelu_exact(hi4.z + bo); hi4.w = gelu_exact(hi4.w + bo);
            *(float4*)&sH[(o0 + 2 * p) * 144 + n0]     = lo4;
            *(float4*)&sH[(o0 + 2 * p + 1) * 144 + n0] = hi4;
        }
    }
    __syncthreads();

    // ---------------- scatter hoisted weights: [W2T | F1T | F2T] ----------------
    {
        #pragma unroll
        for (int k = 0; k < 4; k++) {
            int i = tid + k * TPB;
            if (i < 1024) {
                float4 v = wreg[k];
                if (i < 512) {                    // W2: OUT=32, CIN=64
                    int o = i / 16, c = (i - o * 16) * 4;
                    sW[(c + 0) * 32 + o] = v.x; sW[(c + 1) * 32 + o] = v.y;
                    sW[(c + 2) * 32 + o] = v.z; sW[(c + 3) * 32 + o] = v.w;
                } else if (i < 768) {             // F1: OUT=32, CIN=32
                    int j = i - 512, o = j / 8, c = (j - o * 8) * 4;
                    float* d = sW + 2048;
                    d[(c + 0) * 32 + o] = v.x; d[(c + 1) * 32 + o] = v.y;
                    d[(c + 2) * 32 + o] = v.z; d[(c + 3) * 32 + o] = v.w;
                } else {                          // F2: OUT=32, CIN=32
                    int j = i - 768, o = j / 8, c = (j - o * 8) * 4;
                    float* d = sW + 3072;
                    d[(c + 0) * 32 + o] = v.x; d[(c + 1) * 32 + o] = v.y;
                    d[(c + 2) * 32 + o] = v.z; d[(c + 3) * 32 + o] = v.w;
                }
            }
        }
    }
    __syncthreads();

    // ---------------- fc2 + residual -> sT (in place) ----------------
    {
        int o0 = q << 2;
        float4 a[4];
        gemm4x4T<64, 32>(sW, sH, o0, n0, a);
        #pragma unroll
        for (int j = 0; j < 4; j++) {
            float bb = sB[96 + o0 + j];
            float4 t = *(float4*)&sT[(o0 + j) * 144 + n0];
            a[j].x += bb + t.x; a[j].y += bb + t.y; a[j].z += bb + t.z; a[j].w += bb + t.w;
            *(float4*)&sT[(o0 + j) * 144 + n0] = a[j];
        }
    }
    __syncthreads();

    // ---------------- FFN fc1 -> sS rows 0..31 ----------------
    {
        int o0 = q << 2;
        float4 a[4];
        gemm4x4T<32, 32>(sW + 2048, sT, o0, n0, a);
        #pragma unroll
        for (int j = 0; j < 4; j++) {
            float bb = sB[128 + o0 + j];
            a[j].x = gelu_exact(a[j].x + bb); a[j].y = gelu_exact(a[j].y + bb);
            a[j].z = gelu_exact(a[j].z + bb); a[j].w = gelu_exact(a[j].w + bb);
            *(float4*)&sS[(o0 + j) * 144 + n0] = a[j];
        }
    }
    __syncthreads();

    // ---------------- FFN fc2 + residual -> global ----------------
    {
        int o0 = q << 2;
        float4 a[4];
        gemm4x4T<32, 32>(sW + 3072, sS, o0, n0, a);
        float* go = gout + (size_t)b * 4608;
        #pragma unroll
        for (int j = 0; j < 4; j++) {
            float bb = sB[160 + o0 + j];
            float4 t = *(float4*)&sT[(o0 + j) * 144 + n0];
            a[j].x += bb + t.x; a[j].y += bb + t.y; a[j].z += bb + t.z; a[j].w += bb + t.w;
            *(float4*)&go[(o0 + j) * 144 + n0] = a[j];
        }
    }
}

extern "C" void kernel_launch(void* const* d_in, const int* in_sizes, int n_in,
                              void* d_out, int out_size) {
    (void)n_in; (void)out_size;
    int B = in_sizes[0] / (32 * 144);
    cudaFuncSetAttribute(gcn_kernel, cudaFuncAttributeMaxDynamicSharedMemorySize, SMEM_BYTES);
    gcn_kernel<<<B, TPB, SMEM_BYTES>>>(
        (const float*)d_in[0],  (const float*)d_in[1],  (const float*)d_in[2],
        (const float*)d_in[3],  (const float*)d_in[4],
        (const float*)d_in[5],  (const float*)d_in[6],
        (const float*)d_in[7],  (const float*)d_in[8],
        (const float*)d_in[9],  (const float*)d_in[10],
        (const float*)d_in[11], (const float*)d_in[12],
        (float*)d_out);
}

// round 13
// speedup vs baseline: 1.0211x; 1.0013x over previous
#include <cuda_runtime.h>
#include <math.h>

#define TPB 288
#define SMEM_FLOATS 27328
#define SMEM_BYTES (SMEM_FLOATS * 4)   // 109312 B -> 2 CTAs/SM

typedef unsigned long long ull;

__device__ __forceinline__ float gelu_exact(float x) {
    return 0.5f * x * (1.0f + erff(x * 0.70710678118654752440f));
}

__device__ __forceinline__ ull mul2(ull a, ull b) {
    ull d; asm("mul.rn.f32x2 %0, %1, %2;" : "=l"(d) : "l"(a), "l"(b)); return d;
}
__device__ __forceinline__ ull fma2(ull a, ull b, ull c) {
    ull d; asm("fma.rn.f32x2 %0, %1, %2, %3;" : "=l"(d) : "l"(a), "l"(b), "l"(c)); return d;
}
__device__ __forceinline__ void unpack2(ull v, float& lo, float& hi) {
    unsigned int l, h;
    asm("mov.b64 {%0, %1}, %2;" : "=r"(l), "=r"(h) : "l"(v));
    lo = __uint_as_float(l); hi = __uint_as_float(h);
}
__device__ __forceinline__ ull pack2(float x) {
    ull d; asm("mov.b64 %0, {%1, %1};" : "=l"(d) : "f"(x)); return d;
}

// cooperative transposed weight load: g[o][c] row-major -> s[c][OUT]
template<int OUT, int CIN>
__device__ __forceinline__ void load_wT(const float* __restrict__ g, float* __restrict__ s,
                                        int tid) {
    constexpr int NQ = OUT * CIN / 4;
    for (int i = tid; i < NQ; i += TPB) {
        float4 v = ((const float4*)g)[i];
        int o = i / (CIN / 4);
        int c = (i - o * (CIN / 4)) * 4;
        s[(c + 0) * OUT + o] = v.x;
        s[(c + 1) * OUT + o] = v.y;
        s[(c + 2) * OUT + o] = v.z;
        s[(c + 3) * OUT + o] = v.w;
    }
}

// 4-output x 4-n register tile; weights transposed [c][OUT]; c ascending (R2 numerics)
template<int CIN, int OUT>
__device__ __forceinline__ void gemm4x4T(const float* __restrict__ Wt,
                                         const float* __restrict__ X,
                                         int o0, int n0, float4 a[4]) {
    a[0] = make_float4(0.f, 0.f, 0.f, 0.f);
    a[1] = a[0]; a[2] = a[0]; a[3] = a[0];
    #pragma unroll 8
    for (int c = 0; c < CIN; c++) {
        float4 w = *(const float4*)&Wt[c * OUT + o0];
        float4 v = *(const float4*)&X[c * 144 + n0];
        a[0].x = fmaf(w.x, v.x, a[0].x); a[0].y = fmaf(w.x, v.y, a[0].y);
        a[0].z = fmaf(w.x, v.z, a[0].z); a[0].w = fmaf(w.x, v.w, a[0].w);
        a[1].x = fmaf(w.y, v.x, a[1].x); a[1].y = fmaf(w.y, v.y, a[1].y);
        a[1].z = fmaf(w.y, v.z, a[1].z); a[1].w = fmaf(w.y, v.w, a[1].w);
        a[2].x = fmaf(w.z, v.x, a[2].x); a[2].y = fmaf(w.z, v.y, a[2].y);
        a[2].z = fmaf(w.z, v.z, a[2].z); a[2].w = fmaf(w.z, v.w, a[2].w);
        a[3].x = fmaf(w.w, v.x, a[3].x); a[3].y = fmaf(w.w, v.y, a[3].y);
        a[3].z = fmaf(w.w, v.z, a[3].z); a[3].w = fmaf(w.w, v.w, a[3].w);
    }
}

__global__ void __launch_bounds__(TPB, 2) gcn_kernel(
    const float* __restrict__ gin,  const float* __restrict__ gpos, const float* __restrict__ grel,
    const float* __restrict__ gW1,  const float* __restrict__ gb1,
    const float* __restrict__ gWc,  const float* __restrict__ gbc,
    const float* __restrict__ gW2,  const float* __restrict__ gb2,
    const float* __restrict__ gF1,  const float* __restrict__ gfb1,
    const float* __restrict__ gF2,  const float* __restrict__ gfb2,
    float* __restrict__ gout)
{
    extern __shared__ float sm[];
    float* sW = sm;                   // 4096: W1T -> WcT -> [W2T | F1T | F2T]
    float* sB = sW + 4096;            // 192 biases
    float* sT = sB + 192;             // 4608: tmp = in+pos; later grapher output [c][n]
    float* sS = sT + 4608;            // 9216: stacked [2C][n]; later ffn hidden rows 0..31
    float* sU = sS + 9216;            // 9216: union { sXn/sSq/sIdx/merge | sH conv out }
    float* sXn = sU;                  // [n][c] stride 36
    float* sSq = sU + 5184;           // 144
    int*   sIdx = (int*)(sU + 5376);  // 144*9 ints -> ends at sU+5700
    float* sMrgD = sU + 5704;         // 144*9 floats (part-1 staging)
    int*   sMrgI = (int*)(sU + 7000); // 144*9 ints   -> ends at sU+8296 < 9216
    float* sH = sU;                   // conv output [64][n]

    const int tid = threadIdx.x;
    const int b   = blockIdx.x;
    const int q   = tid / 36;         // 0..7
    const int r   = tid - q * 36;     // 0..35
    const int n0  = r << 2;

    // ---------------- stage 0: W1T + biases + input(+pos) ----------------
    load_wT<32, 32>(gW1, sW, tid);
    if (tid < 32)       sB[tid] = gb1[tid];
    else if (tid < 96)  sB[tid] = gbc[tid - 32];
    else if (tid < 128) sB[tid] = gb2[tid - 96];
    else if (tid < 160) sB[tid] = gfb1[tid - 128];
    else if (tid < 192) sB[tid] = gfb2[tid - 160];
    {
        const float4* gi4 = (const float4*)(gin + (size_t)b * 4608);
        const float4* gp4 = (const float4*)gpos;
        for (int i = tid; i < 1152; i += TPB) {
            float4 a = gi4[i], p = gp4[i];
            a.x += p.x; a.y += p.y; a.z += p.z; a.w += p.w;
            ((float4*)sT)[i] = a;
        }
    }
    __syncthreads();

    // ---------------- fc1: xf = W1 @ tmp + b1 -> sS even rows ----------------
    {
        int o0 = q << 2;
        float4 a[4];
        gemm4x4T<32, 32>(sW, sT, o0, n0, a);
        #pragma unroll
        for (int j = 0; j < 4; j++) {
            float bb = sB[o0 + j];
            a[j].x += bb; a[j].y += bb; a[j].z += bb; a[j].w += bb;
            *(float4*)&sS[(2 * (o0 + j)) * 144 + n0] = a[j];
        }
    }
    __syncthreads();

    // ---------------- normalize (tid<144) in parallel with WcT load ----------------
    if (tid < 144) {
        float v[32]; float s = 0.f;
        #pragma unroll
        for (int c = 0; c < 32; c++) { float x = sS[(2 * c) * 144 + tid]; v[c] = x; s = fmaf(x, x, s); }
        float nrm = fmaxf(sqrtf(s), 1e-12f);
        float sq = 0.f;
        #pragma unroll
        for (int c = 0; c < 32; c++) { float xn = v[c] / nrm; sXn[tid * 36 + c] = xn; sq = fmaf(xn, xn, sq); }
        sSq[tid] = sq;
    } else {
        // WcT: 64x64 -> [c][64]
        constexpr int NQ = 64 * 64 / 4;
        for (int i = tid - 144; i < NQ; i += TPB - 144) {
            float4 v = ((const float4*)gWc)[i];
            int o = i / 16;
            int c = (i - o * 16) * 4;
            sW[(c + 0) * 64 + o] = v.x;
            sW[(c + 1) * 64 + o] = v.y;
            sW[(c + 2) * 64 + o] = v.z;
            sW[(c + 3) * 64 + o] = v.w;
        }
    }
    __syncthreads();

    // ---------------- pairwise dist + top-9, software-pipelined 1 deep ----------------
    // Pair t+1's dots (grel LDGs issued first) compute BEFORE pair t's serial insert
    // chains -> independent FFMA2/LDS/LDG stream covers the sort latency.
    {
        const int row  = (tid < 144) ? tid : tid - 144;
        const int part = (tid < 144) ? 0 : 1;
        ull vv[16];                              // all 32 channels as 16 packed pairs
        {
            const ulonglong2* xr2 = (const ulonglong2*)&sXn[row * 36];
            #pragma unroll
            for (int i = 0; i < 8; i++) { ulonglong2 t = xr2[i]; vv[2*i] = t.x; vv[2*i+1] = t.y; }
        }
        const float sqn = sSq[row];
        const int m0 = part * 72;

        // distances for the pair starting at absolute index m (chains == R2's d0..d3)
        auto dot_pair = [&](int m, float& dA, float& dB) {
            float relA = __ldg(&grel[(size_t)m * 144 + row]);          // issue LDGs first
            float relB = __ldg(&grel[(size_t)(m + 1) * 144 + row]);
            const ulonglong2* xa2 = (const ulonglong2*)&sXn[m * 36];
            const ulonglong2* xb2 = xa2 + 9;                           // next row (36 floats)
            ulonglong2 t = xa2[0];
            ull a01 = mul2(vv[0], t.x);
            ull a23 = mul2(vv[1], t.y);
            ulonglong2 u = xb2[0];
            ull b01 = mul2(vv[0], u.x);
            ull b23 = mul2(vv[1], u.y);
            #pragma unroll
            for (int i = 1; i < 8; i++) {
                t = xa2[i];
                a01 = fma2(vv[2*i],   t.x, a01);
                a23 = fma2(vv[2*i+1], t.y, a23);
                u = xb2[i];
                b01 = fma2(vv[2*i],   u.x, b01);
                b23 = fma2(vv[2*i+1], u.y, b23);
            }
            float a0, a1, a2, a3, e0, e1, e2, e3;
            unpack2(a01, a0, a1); unpack2(a23, a2, a3);
            unpack2(b01, e0, e1); unpack2(b23, e2, e3);
            float dota = (a0 + a1) + (a2 + a3);
            float dotb = (e0 + e1) + (e2 + e3);
            dA = (sqn - 2.0f * dota) + sSq[m]     + relA;
            dB = (sqn - 2.0f * dotb) + sSq[m + 1] + relB;
        };

        float bd[9]; int bi[9];
        #pragma unroll
        for (int k = 0; k < 9; k++) { bd[k] = 3.0e38f; bi[k] = 0; }

        float dcur0, dcur1;
        dot_pair(m0, dcur0, dcur1);                 // prologue
        for (int mm = 0; mm < 72; mm += 2) {
            const int m = m0 + mm;
            float dnxt0 = 0.f, dnxt1 = 0.f;
            if (mm < 70) dot_pair(m + 2, dnxt0, dnxt1);   // next pair in flight over inserts
            // insert m first, then m+1 (ascending order preserves lax.top_k tie rule)
            if (dcur0 < bd[8]) {
                bd[8] = dcur0; bi[8] = m;
                #pragma unroll
                for (int j = 8; j > 0; --j) {
                    if (bd[j] < bd[j-1]) {
                        float td = bd[j]; bd[j] = bd[j-1]; bd[j-1] = td;
                        int   ti = bi[j]; bi[j] = bi[j-1]; bi[j-1] = ti;
                    }
                }
            }
            if (dcur1 < bd[8]) {
                bd[8] = dcur1; bi[8] = m + 1;
                #pragma unroll
                for (int j = 8; j > 0; --j) {
                    if (bd[j] < bd[j-1]) {
                        float td = bd[j]; bd[j] = bd[j-1]; bd[j-1] = td;
                        int   ti = bi[j]; bi[j] = bi[j-1]; bi[j-1] = ti;
                    }
                }
            }
            dcur0 = dnxt0; dcur1 = dnxt1;
        }
        if (part == 1) {                          // stage part-1 lists
            int base = row * 9;
            #pragma unroll
            for (int k = 0; k < 9; k++) { sMrgD[base + k] = bd[k]; sMrgI[base + k] = bi[k]; }
        }
        __syncthreads();
        if (part == 0) {                          // merge (ascending m preserves tie rule)
            int base = row * 9;
            #pragma unroll
            for (int k = 0; k < 9; k++) {
                float d = sMrgD[base + k]; int mi = sMrgI[base + k];
                if (d < bd[8]) {
                    bd[8] = d; bi[8] = mi;
                    #pragma unroll
                    for (int j = 8; j > 0; --j) {
                        if (bd[j] < bd[j-1]) {
                            float td = bd[j]; bd[j] = bd[j-1]; bd[j-1] = td;
                            int   ti = bi[j]; bi[j] = bi[j-1]; bi[j-1] = ti;
                        }
                    }
                }
            }
            #pragma unroll
            for (int k = 0; k < 9; k++) sIdx[row * 9 + k] = bi[k];
        }
    }
    __syncthreads();

    // ---------------- MRConv: max over gathers, then subtract (bit-identical) ----------------
    {
        const int n2 = tid % 144;
        const int g  = tid / 144;          // 0..1 -> channels g*16..g*16+15
        int idx9[9];
        #pragma unroll
        for (int k = 0; k < 9; k++) idx9[k] = sIdx[n2 * 9 + k];
        #pragma unroll
        for (int cc = 0; cc < 16; cc++) {
            int c = g * 16 + cc;
            const float* xrow = &sS[(2 * c) * 144];
            float mx = xrow[idx9[0]];
            #pragma unroll
            for (int k = 1; k < 9; k++) mx = fmaxf(mx, xrow[idx9[k]]);
            sS[(2 * c + 1) * 144 + n2] = mx - xrow[n2];
        }
    }
    __syncthreads();

    // ---------------- hoist W2/F1/F2 LDGs (stores happen after conv barrier) ----------------
    float4 wreg[4];
    {
        #pragma unroll
        for (int k = 0; k < 4; k++) {
            int i = tid + k * TPB;
            if (i < 1024) {
                if (i < 512)      wreg[k] = ((const float4*)gW2)[i];
                else if (i < 768) wreg[k] = ((const float4*)gF1)[i - 512];
                else              wreg[k] = ((const float4*)gF2)[i - 768];
            }
        }
    }

    // ---------------- conv: hc = gelu(WcT @ stacked + bc), 8o x 4n, FFMA2-packed ----------------
    {
        const int o0 = q << 3;             // 0..56
        ull A[4][4];                       // [output-pair p][n]
        #pragma unroll
        for (int p = 0; p < 4; p++)
            #pragma unroll
            for (int n = 0; n < 4; n++) A[p][n] = 0ULL;
        #pragma unroll 4
        for (int c = 0; c < 64; c++) {
            ulonglong2 wa = *(const ulonglong2*)&sW[c * 64 + o0];      // pairs (o0,o0+1),(o0+2,o0+3)
            ulonglong2 wb = *(const ulonglong2*)&sW[c * 64 + o0 + 4];  // pairs (o0+4,o0+5),(o0+6,o0+7)
            float4 v = *(const float4*)&sS[c * 144 + n0];
            ull vd0 = pack2(v.x), vd1 = pack2(v.y), vd2 = pack2(v.z), vd3 = pack2(v.w);
            A[0][0] = fma2(wa.x, vd0, A[0][0]); A[0][1] = fma2(wa.x, vd1, A[0][1]);
            A[0][2] = fma2(wa.x, vd2, A[0][2]); A[0][3] = fma2(wa.x, vd3, A[0][3]);
            A[1][0] = fma2(wa.y, vd0, A[1][0]); A[1][1] = fma2(wa.y, vd1, A[1][1]);
            A[1][2] = fma2(wa.y, vd2, A[1][2]); A[1][3] = fma2(wa.y, vd3, A[1][3]);
            A[2][0] = fma2(wb.x, vd0, A[2][0]); A[2][1] = fma2(wb.x, vd1, A[2][1]);
            A[2][2] = fma2(wb.x, vd2, A[2][2]); A[2][3] = fma2(wb.x, vd3, A[2][3]);
            A[3][0] = fma2(wb.y, vd0, A[3][0]); A[3][1] = fma2(wb.y, vd1, A[3][1]);
            A[3][2] = fma2(wb.y, vd2, A[3][2]); A[3][3] = fma2(wb.y, vd3, A[3][3]);
        }
        #pragma unroll
        for (int p = 0; p < 4; p++) {
            float4 lo4, hi4;
            unpack2(A[p][0], lo4.x, hi4.x);
            unpack2(A[p][1], lo4.y, hi4.y);
            unpack2(A[p][2], lo4.z, hi4.z);
            unpack2(A[p][3], lo4.w, hi4.w);
            float be = sB[32 + o0 + 2 * p];
            float bo = sB[32 + o0 + 2 * p + 1];
            lo4.x = gelu_exact(lo4.x + be); lo4.y = gelu_exact(lo4.y + be);
            lo4.z = gelu_exact(lo4.z + be); lo4.w = gelu_exact(lo4.w + be);
            hi4.x = gelu_exact(hi4.x + bo); hi4.y = gelu_exact(hi4.y + bo);
            hi4.z = gelu_exact(hi4.z + bo); hi4.w = gelu_exact(hi4.w + bo);
            *(float4*)&sH[(o0 + 2 * p) * 144 + n0]     = lo4;
            *(float4*)&sH[(o0 + 2 * p + 1) * 144 + n0] = hi4;
        }
    }
    __syncthreads();

    // ---------------- scatter hoisted weights: [W2T | F1T | F2T] ----------------
    {
        #pragma unroll
        for (int k = 0; k < 4; k++) {
            int i = tid + k * TPB;
            if (i < 1024) {
                float4 v = wreg[k];
                if (i < 512) {                    // W2: OUT=32, CIN=64
                    int o = i / 16, c = (i - o * 16) * 4;
                    sW[(c + 0) * 32 + o] = v.x; sW[(c + 1) * 32 + o] = v.y;
                    sW[(c + 2) * 32 + o] = v.z; sW[(c + 3) * 32 + o] = v.w;
                } else if (i < 768) {             // F1: OUT=32, CIN=32
                    int j = i - 512, o = j / 8, c = (j - o * 8) * 4;
                    float* d = sW + 2048;
                    d[(c + 0) * 32 + o] = v.x; d[(c + 1) * 32 + o] = v.y;
                    d[(c + 2) * 32 + o] = v.z; d[(c + 3) * 32 + o] = v.w;
                } else {                          // F2: OUT=32, CIN=32
                    int j = i - 768, o = j / 8, c = (j - o * 8) * 4;
                    float* d = sW + 3072;
                    d[(c + 0) * 32 + o] = v.x; d[(c + 1) * 32 + o] = v.y;
                    d[(c + 2) * 32 + o] = v.z; d[(c + 3) * 32 + o] = v.w;
                }
            }
        }
    }
    __syncthreads();

    // ---------------- fc2 + residual -> sT (in place) ----------------
    {
        int o0 = q << 2;
        float4 a[4];
        gemm4x4T<64, 32>(sW, sH, o0, n0, a);
        #pragma unroll
        for (int j = 0; j < 4; j++) {
            float bb = sB[96 + o0 + j];
            float4 t = *(float4*)&sT[(o0 + j) * 144 + n0];
            a[j].x += bb + t.x; a[j].y += bb + t.y; a[j].z += bb + t.z; a[j].w += bb + t.w;
            *(float4*)&sT[(o0 + j) * 144 + n0] = a[j];
        }
    }
    __syncthreads();

    // ---------------- FFN fc1 -> sS rows 0..31 ----------------
    {
        int o0 = q << 2;
        float4 a[4];
        gemm4x4T<32, 32>(sW + 2048, sT, o0, n0, a);
        #pragma unroll
        for (int j = 0; j < 4; j++) {
            float bb = sB[128 + o0 + j];
            a[j].x = gelu_exact(a[j].x + bb); a[j].y = gelu_exact(a[j].y + bb);
            a[j].z = gelu_exact(a[j].z + bb); a[j].w = gelu_exact(a[j].w + bb);
            *(float4*)&sS[(o0 + j) * 144 + n0] = a[j];
        }
    }
    __syncthreads();

    // ---------------- FFN fc2 + residual -> global ----------------
    {
        int o0 = q << 2;
        float4 a[4];
        gemm4x4T<32, 32>(sW + 3072, sS, o0, n0, a);
        float* go = gout + (size_t)b * 4608;
        #pragma unroll
        for (int j = 0; j < 4; j++) {
            float bb = sB[160 + o0 + j];
            float4 t = *(float4*)&sT[(o0 + j) * 144 + n0];
            a[j].x += bb + t.x; a[j].y += bb + t.y; a[j].z += bb + t.z; a[j].w += bb + t.w;
            *(float4*)&go[(o0 + j) * 144 + n0] = a[j];
        }
    }
}

extern "C" void kernel_launch(void* const* d_in, const int* in_sizes, int n_in,
                              void* d_out, int out_size) {
    (void)n_in; (void)out_size;
    int B = in_sizes[0] / (32 * 144);
    cudaFuncSetAttribute(gcn_kernel, cudaFuncAttributeMaxDynamicSharedMemorySize, SMEM_BYTES);
    gcn_kernel<<<B, TPB, SMEM_BYTES>>>(
        (const float*)d_in[0],  (const float*)d_in[1],  (const float*)d_in[2],
        (const float*)d_in[3],  (const float*)d_in[4],
        (const float*)d_in[5],  (const float*)d_in[6],
        (const float*)d_in[7],  (const float*)d_in[8],
        (const float*)d_in[9],  (const float*)d_in[10],
        (const float*)d_in[11], (const float*)d_in[12],
        (float*)d_out);
}

// round 15
// speedup vs baseline: 1.0736x; 1.0514x over previous
#include <cuda_runtime.h>
#include <math.h>

#define TPB 288
#define SMEM_FLOATS 27328
#define SMEM_BYTES (SMEM_FLOATS * 4)   // 109312 B -> 2 CTAs/SM

typedef unsigned long long ull;

__device__ __forceinline__ float gelu_exact(float x) {
    return 0.5f * x * (1.0f + erff(x * 0.70710678118654752440f));
}

__device__ __forceinline__ ull mul2(ull a, ull b) {
    ull d; asm("mul.rn.f32x2 %0, %1, %2;" : "=l"(d) : "l"(a), "l"(b)); return d;
}
__device__ __forceinline__ ull fma2(ull a, ull b, ull c) {
    ull d; asm("fma.rn.f32x2 %0, %1, %2, %3;" : "=l"(d) : "l"(a), "l"(b), "l"(c)); return d;
}
__device__ __forceinline__ void unpack2(ull v, float& lo, float& hi) {
    unsigned int l, h;
    asm("mov.b64 {%0, %1}, %2;" : "=r"(l), "=r"(h) : "l"(v));
    lo = __uint_as_float(l); hi = __uint_as_float(h);
}
__device__ __forceinline__ ull pack2(float x) {
    ull d; asm("mov.b64 %0, {%1, %1};" : "=l"(d) : "f"(x)); return d;
}

// Latency-flat sorted-insert: bd'[j]=min(max(d,bd[j-1]),bd[j]) — all levels depend
// only on OLD bd and d (no serial compare->swap chain). Exact, stable (ties keep
// earlier/lower-m element), and a no-op when d >= bd[8] so no guard is needed.
__device__ __forceinline__ void insert9(float bd[9], int bi[9], float d, int mi) {
    bool p[9];
    #pragma unroll
    for (int j = 0; j < 9; j++) p[j] = d < bd[j];
    #pragma unroll
    for (int j = 8; j >= 1; --j) bd[j] = fminf(fmaxf(d, bd[j-1]), bd[j]);
    bd[0] = fminf(d, bd[0]);
    #pragma unroll
    for (int j = 8; j >= 1; --j) bi[j] = p[j-1] ? bi[j-1] : (p[j] ? mi : bi[j]);
    bi[0] = p[0] ? mi : bi[0];
}

// cooperative transposed weight load: g[o][c] row-major -> s[c][OUT]
template<int OUT, int CIN>
__device__ __forceinline__ void load_wT(const float* __restrict__ g, float* __restrict__ s,
                                        int tid) {
    constexpr int NQ = OUT * CIN / 4;
    for (int i = tid; i < NQ; i += TPB) {
        float4 v = ((const float4*)g)[i];
        int o = i / (CIN / 4);
        int c = (i - o * (CIN / 4)) * 4;
        s[(c + 0) * OUT + o] = v.x;
        s[(c + 1) * OUT + o] = v.y;
        s[(c + 2) * OUT + o] = v.z;
        s[(c + 3) * OUT + o] = v.w;
    }
}

// 4-output x 4-n register tile; weights transposed [c][OUT]; c ascending (R2 numerics)
template<int CIN, int OUT>
__device__ __forceinline__ void gemm4x4T(const float* __restrict__ Wt,
                                         const float* __restrict__ X,
                                         int o0, int n0, float4 a[4]) {
    a[0] = make_float4(0.f, 0.f, 0.f, 0.f);
    a[1] = a[0]; a[2] = a[0]; a[3] = a[0];
    #pragma unroll 8
    for (int c = 0; c < CIN; c++) {
        float4 w = *(const float4*)&Wt[c * OUT + o0];
        float4 v = *(const float4*)&X[c * 144 + n0];
        a[0].x = fmaf(w.x, v.x, a[0].x); a[0].y = fmaf(w.x, v.y, a[0].y);
        a[0].z = fmaf(w.x, v.z, a[0].z); a[0].w = fmaf(w.x, v.w, a[0].w);
        a[1].x = fmaf(w.y, v.x, a[1].x); a[1].y = fmaf(w.y, v.y, a[1].y);
        a[1].z = fmaf(w.y, v.z, a[1].z); a[1].w = fmaf(w.y, v.w, a[1].w);
        a[2].x = fmaf(w.z, v.x, a[2].x); a[2].y = fmaf(w.z, v.y, a[2].y);
        a[2].z = fmaf(w.z, v.z, a[2].z); a[2].w = fmaf(w.z, v.w, a[2].w);
        a[3].x = fmaf(w.w, v.x, a[3].x); a[3].y = fmaf(w.w, v.y, a[3].y);
        a[3].z = fmaf(w.w, v.z, a[3].z); a[3].w = fmaf(w.w, v.w, a[3].w);
    }
}

__global__ void __launch_bounds__(TPB, 2) gcn_kernel(
    const float* __restrict__ gin,  const float* __restrict__ gpos, const float* __restrict__ grel,
    const float* __restrict__ gW1,  const float* __restrict__ gb1,
    const float* __restrict__ gWc,  const float* __restrict__ gbc,
    const float* __restrict__ gW2,  const float* __restrict__ gb2,
    const float* __restrict__ gF1,  const float* __restrict__ gfb1,
    const float* __restrict__ gF2,  const float* __restrict__ gfb2,
    float* __restrict__ gout)
{
    extern __shared__ float sm[];
    float* sW = sm;                   // 4096: W1T -> WcT -> [W2T | F1T | F2T]
    float* sB = sW + 4096;            // 192 biases
    float* sT = sB + 192;             // 4608: tmp = in+pos; later grapher output [c][n]
    float* sS = sT + 4608;            // 9216: stacked [2C][n]; later ffn hidden rows 0..31
    float* sU = sS + 9216;            // 9216: union { dist scratch | sH conv out }
    // FIXED non-overlapping layout (sIdx is 1296 INTS = 1296 float-slots!):
    float* sXn  = sU;                 // [0, 5184)      normalized nodes [n][c] stride 36
    float* sSq  = sU + 5184;          // [5184, 5328)
    int*   sIdx = (int*)(sU + 5328);  // [5328, 6624)
    float* sMrgD = sU + 6624;         // [6624, 7920)   part-1 staging dists
    int*   sMrgI = (int*)(sU + 7920); // [7920, 9216)   part-1 staging indices
    float* sH = sU;                   // conv output [64][n] (after dist scratch dead)

    const int tid = threadIdx.x;
    const int b   = blockIdx.x;
    const int q   = tid / 36;         // 0..7
    const int r   = tid - q * 36;     // 0..35
    const int n0  = r << 2;

    // ---------------- stage 0: W1T + biases + input(+pos) ----------------
    load_wT<32, 32>(gW1, sW, tid);
    if (tid < 32)       sB[tid] = gb1[tid];
    else if (tid < 96)  sB[tid] = gbc[tid - 32];
    else if (tid < 128) sB[tid] = gb2[tid - 96];
    else if (tid < 160) sB[tid] = gfb1[tid - 128];
    else if (tid < 192) sB[tid] = gfb2[tid - 160];
    {
        const float4* gi4 = (const float4*)(gin + (size_t)b * 4608);
        const float4* gp4 = (const float4*)gpos;
        for (int i = tid; i < 1152; i += TPB) {
            float4 a = gi4[i], p = gp4[i];
            a.x += p.x; a.y += p.y; a.z += p.z; a.w += p.w;
            ((float4*)sT)[i] = a;
        }
    }
    __syncthreads();

    // ---------------- fc1: xf = W1 @ tmp + b1 -> sS even rows ----------------
    {
        int o0 = q << 2;
        float4 a[4];
        gemm4x4T<32, 32>(sW, sT, o0, n0, a);
        #pragma unroll
        for (int j = 0; j < 4; j++) {
            float bb = sB[o0 + j];
            a[j].x += bb; a[j].y += bb; a[j].z += bb; a[j].w += bb;
            *(float4*)&sS[(2 * (o0 + j)) * 144 + n0] = a[j];
        }
    }
    __syncthreads();

    // ---------------- normalize (tid<144) in parallel with WcT load ----------------
    if (tid < 144) {
        float v[32]; float s = 0.f;
        #pragma unroll
        for (int c = 0; c < 32; c++) { float x = sS[(2 * c) * 144 + tid]; v[c] = x; s = fmaf(x, x, s); }
        float nrm = fmaxf(sqrtf(s), 1e-12f);
        float sq = 0.f;
        #pragma unroll
        for (int c = 0; c < 32; c++) { float xn = v[c] / nrm; sXn[tid * 36 + c] = xn; sq = fmaf(xn, xn, sq); }
        sSq[tid] = sq;
    } else {
        // WcT: 64x64 -> [c][64]
        constexpr int NQ = 64 * 64 / 4;
        for (int i = tid - 144; i < NQ; i += TPB - 144) {
            float4 v = ((const float4*)gWc)[i];
            int o = i / 16;
            int c = (i - o * 16) * 4;
            sW[(c + 0) * 64 + o] = v.x;
            sW[(c + 1) * 64 + o] = v.y;
            sW[(c + 2) * 64 + o] = v.z;
            sW[(c + 3) * 64 + o] = v.w;
        }
    }
    __syncthreads();

    // ---------------- pairwise dist + top-9 ----------------
    // part-major broadcast layout; m-loop unrolled x2; latency-flat inserts (no guard,
    // no serial compare->swap chain).
    {
        const int row  = (tid < 144) ? tid : tid - 144;
        const int part = (tid < 144) ? 0 : 1;
        ull vv[16];                              // all 32 channels as 16 packed pairs
        {
            const ulonglong2* xr2 = (const ulonglong2*)&sXn[row * 36];
            #pragma unroll
            for (int i = 0; i < 8; i++) { ulonglong2 t = xr2[i]; vv[2*i] = t.x; vv[2*i+1] = t.y; }
        }
        const float sqn = sSq[row];
        float bd[9]; int bi[9];
        #pragma unroll
        for (int k = 0; k < 9; k++) { bd[k] = 3.0e38f; bi[k] = 0; }
        const int m0 = part * 72;
        const float* relp = grel + (size_t)m0 * 144 + row;
        float relv0 = relp[0];
        float relv1 = relp[144];
        relp += 288;
        for (int mm = 0; mm < 72; mm += 2) {
            const int m = m0 + mm;
            float reln0 = 0.f, reln1 = 0.f;
            if (mm < 70) { reln0 = relp[0]; reln1 = relp[144]; }   // prefetch next pair
            relp += 288;
            const ulonglong2* xa2 = (const ulonglong2*)&sXn[m * 36];
            const ulonglong2* xb2 = (const ulonglong2*)&sXn[(m + 1) * 36];
            ulonglong2 t = xa2[0];
            ull a01 = mul2(vv[0], t.x);
            ull a23 = mul2(vv[1], t.y);
            ulonglong2 u = xb2[0];
            ull b01 = mul2(vv[0], u.x);
            ull b23 = mul2(vv[1], u.y);
            #pragma unroll
            for (int i = 1; i < 8; i++) {
                t = xa2[i];
                a01 = fma2(vv[2*i],   t.x, a01);
                a23 = fma2(vv[2*i+1], t.y, a23);
                u = xb2[i];
                b01 = fma2(vv[2*i],   u.x, b01);
                b23 = fma2(vv[2*i+1], u.y, b23);
            }
            float a0, a1, a2, a3, e0, e1, e2, e3;
            unpack2(a01, a0, a1); unpack2(a23, a2, a3);
            unpack2(b01, e0, e1); unpack2(b23, e2, e3);
            float dota = (a0 + a1) + (a2 + a3);
            float dotb = (e0 + e1) + (e2 + e3);
            float da = (sqn - 2.0f * dota) + sSq[m]     + relv0;
            float db = (sqn - 2.0f * dotb) + sSq[m + 1] + relv1;
            relv0 = reln0; relv1 = reln1;
            // ascending m order preserves lax.top_k tie rule
            insert9(bd, bi, da, m);
            insert9(bd, bi, db, m + 1);
        }
        if (part == 1) {                          // stage part-1 lists
            int base = row * 9;
            #pragma unroll
            for (int k = 0; k < 9; k++) { sMrgD[base + k] = bd[k]; sMrgI[base + k] = bi[k]; }
        }
        __syncthreads();
        if (part == 0) {                          // merge (ascending m preserves tie rule)
            int base = row * 9;
            #pragma unroll
            for (int k = 0; k < 9; k++) {
                insert9(bd, bi, sMrgD[base + k], sMrgI[base + k]);
            }
            #pragma unroll
            for (int k = 0; k < 9; k++) sIdx[row * 9 + k] = bi[k];
        }
    }
    __syncthreads();

    // ---------------- MRConv: max over gathers, then subtract (bit-identical) ----------------
    {
        const int n2 = tid % 144;
        const int g  = tid / 144;          // 0..1 -> channels g*16..g*16+15
        int idx9[9];
        #pragma unroll
        for (int k = 0; k < 9; k++) idx9[k] = sIdx[n2 * 9 + k];
        #pragma unroll
        for (int cc = 0; cc < 16; cc++) {
            int c = g * 16 + cc;
            const float* xrow = &sS[(2 * c) * 144];
            float mx = xrow[idx9[0]];
            #pragma unroll
            for (int k = 1; k < 9; k++) mx = fmaxf(mx, xrow[idx9[k]]);
            sS[(2 * c + 1) * 144 + n2] = mx - xrow[n2];
        }
    }
    __syncthreads();

    // ---------------- hoist W2/F1/F2 LDGs (stores happen after conv barrier) ----------------
    float4 wreg[4];
    {
        #pragma unroll
        for (int k = 0; k < 4; k++) {
            int i = tid + k * TPB;
            if (i < 1024) {
                if (i < 512)      wreg[k] = ((const float4*)gW2)[i];
                else if (i < 768) wreg[k] = ((const float4*)gF1)[i - 512];
                else              wreg[k] = ((const float4*)gF2)[i - 768];
            }
        }
    }

    // ---------------- conv: hc = gelu(WcT @ stacked + bc), 8o x 4n, FFMA2-packed ----------------
    {
        const int o0 = q << 3;             // 0..56
        ull A[4][4];                       // [output-pair p][n]
        #pragma unroll
        for (int p = 0; p < 4; p++)
            #pragma unroll
            for (int n = 0; n < 4; n++) A[p][n] = 0ULL;
        #pragma unroll 4
        for (int c = 0; c < 64; c++) {
            ulonglong2 wa = *(const ulonglong2*)&sW[c * 64 + o0];      // pairs (o0,o0+1),(o0+2,o0+3)
            ulonglong2 wb = *(const ulonglong2*)&sW[c * 64 + o0 + 4];  // pairs (o0+4,o0+5),(o0+6,o0+7)
            float4 v = *(const float4*)&sS[c * 144 + n0];
            ull vd0 = pack2(v.x), vd1 = pack2(v.y), vd2 = pack2(v.z), vd3 = pack2(v.w);
            A[0][0] = fma2(wa.x, vd0, A[0][0]); A[0][1] = fma2(wa.x, vd1, A[0][1]);
            A[0][2] = fma2(wa.x, vd2, A[0][2]); A[0][3] = fma2(wa.x, vd3, A[0][3]);
            A[1][0] = fma2(wa.y, vd0, A[1][0]); A[1][1] = fma2(wa.y, vd1, A[1][1]);
            A[1][2] = fma2(wa.y, vd2, A[1][2]); A[1][3] = fma2(wa.y, vd3, A[1][3]);
            A[2][0] = fma2(wb.x, vd0, A[2][0]); A[2][1] = fma2(wb.x, vd1, A[2][1]);
            A[2][2] = fma2(wb.x, vd2, A[2][2]); A[2][3] = fma2(wb.x, vd3, A[2][3]);
            A[3][0] = fma2(wb.y, vd0, A[3][0]); A[3][1] = fma2(wb.y, vd1, A[3][1]);
            A[3][2] = fma2(wb.y, vd2, A[3][2]); A[3][3] = fma2(wb.y, vd3, A[3][3]);
        }
        #pragma unroll
        for (int p = 0; p < 4; p++) {
            float4 lo4, hi4;
            unpack2(A[p][0], lo4.x, hi4.x);
            unpack2(A[p][1], lo4.y, hi4.y);
            unpack2(A[p][2], lo4.z, hi4.z);
            unpack2(A[p][3], lo4.w, hi4.w);
            float be = sB[32 + o0 + 2 * p];
            float bo = sB[32 + o0 + 2 * p + 1];
            lo4.x = gelu_exact(lo4.x + be); lo4.y = gelu_exact(lo4.y + be);
            lo4.z = gelu_exact(lo4.z + be); lo4.w = gelu_exact(lo4.w + be);
            hi4.x = gelu_exact(hi4.x + bo); hi4.y = gelu_exact(hi4.y + bo);
            hi4.z = gelu_exact(hi4.z + bo); hi4.w = gelu_exact(hi4.w + bo);
            *(float4*)&sH[(o0 + 2 * p) * 144 + n0]     = lo4;
            *(float4*)&sH[(o0 + 2 * p + 1) * 144 + n0] = hi4;
        }
    }
    __syncthreads();

    // ---------------- scatter hoisted weights: [W2T | F1T | F2T] ----------------
    {
        #pragma unroll
        for (int k = 0; k < 4; k++) {
            int i = tid + k * TPB;
            if (i < 1024) {
                float4 v = wreg[k];
                if (i < 512) {                    // W2: OUT=32, CIN=64
                    int o = i / 16, c = (i - o * 16) * 4;
                    sW[(c + 0) * 32 + o] = v.x; sW[(c + 1) * 32 + o] = v.y;
                    sW[(c + 2) * 32 + o] = v.z; sW[(c + 3) * 32 + o] = v.w;
                } else if (i < 768) {             // F1: OUT=32, CIN=32
                    int j = i - 512, o = j / 8, c = (j - o * 8) * 4;
                    float* d = sW + 2048;
                    d[(c + 0) * 32 + o] = v.x; d[(c + 1) * 32 + o] = v.y;
                    d[(c + 2) * 32 + o] = v.z; d[(c + 3) * 32 + o] = v.w;
                } else {                          // F2: OUT=32, CIN=32
                    int j = i - 768, o = j / 8, c = (j - o * 8) * 4;
                    float* d = sW + 3072;
                    d[(c + 0) * 32 + o] = v.x; d[(c + 1) * 32 + o] = v.y;
                    d[(c + 2) * 32 + o] = v.z; d[(c + 3) * 32 + o] = v.w;
                }
            }
        }
    }
    __syncthreads();

    // ---------------- fc2 + residual -> sT (in place) ----------------
    {
        int o0 = q << 2;
        float4 a[4];
        gemm4x4T<64, 32>(sW, sH, o0, n0, a);
        #pragma unroll
        for (int j = 0; j < 4; j++) {
            float bb = sB[96 + o0 + j];
            float4 t = *(float4*)&sT[(o0 + j) * 144 + n0];
            a[j].x += bb + t.x; a[j].y += bb + t.y; a[j].z += bb + t.z; a[j].w += bb + t.w;
            *(float4*)&sT[(o0 + j) * 144 + n0] = a[j];
        }
    }
    __syncthreads();

    // ---------------- FFN fc1 -> sS rows 0..31 ----------------
    {
        int o0 = q << 2;
        float4 a[4];
        gemm4x4T<32, 32>(sW + 2048, sT, o0, n0, a);
        #pragma unroll
        for (int j = 0; j < 4; j++) {
            float bb = sB[128 + o0 + j];
            a[j].x = gelu_exact(a[j].x + bb); a[j].y = gelu_exact(a[j].y + bb);
            a[j].z = gelu_exact(a[j].z + bb); a[j].w = gelu_exact(a[j].w + bb);
            *(float4*)&sS[(o0 + j) * 144 + n0] = a[j];
        }
    }
    __syncthreads();

    // ---------------- FFN fc2 + residual -> global ----------------
    {
        int o0 = q << 2;
        float4 a[4];
        gemm4x4T<32, 32>(sW + 3072, sS, o0, n0, a);
        float* go = gout + (size_t)b * 4608;
        #pragma unroll
        for (int j = 0; j < 4; j++) {
            float bb = sB[160 + o0 + j];
            float4 t = *(float4*)&sT[(o0 + j) * 144 + n0];
            a[j].x += bb + t.x; a[j].y += bb + t.y; a[j].z += bb + t.z; a[j].w += bb + t.w;
            *(float4*)&go[(o0 + j) * 144 + n0] = a[j];
        }
    }
}

extern "C" void kernel_launch(void* const* d_in, const int* in_sizes, int n_in,
                              void* d_out, int out_size) {
    (void)n_in; (void)out_size;
    int B = in_sizes[0] / (32 * 144);
    cudaFuncSetAttribute(gcn_kernel, cudaFuncAttributeMaxDynamicSharedMemorySize, SMEM_BYTES);
    gcn_kernel<<<B, TPB, SMEM_BYTES>>>(
        (const float*)d_in[0],  (const float*)d_in[1],  (const float*)d_in[2],
        (const float*)d_in[3],  (const float*)d_in[4],
        (const float*)d_in[5],  (const float*)d_in[6],
        (const float*)d_in[7],  (const float*)d_in[8],
        (const float*)d_in[9],  (const float*)d_in[10],
        (const float*)d_in[11], (const float*)d_in[12],
        (float*)d_out);
}

// round 16
// speedup vs baseline: 1.1268x; 1.0495x over previous
#include <cuda_runtime.h>
#include <math.h>

#define TPB 288
#define SMEM_FLOATS 27328
#define SMEM_BYTES (SMEM_FLOATS * 4)   // 109312 B -> 2 CTAs/SM

typedef unsigned long long ull;

__device__ __forceinline__ float gelu_exact(float x) {
    return 0.5f * x * (1.0f + erff(x * 0.70710678118654752440f));
}

__device__ __forceinline__ ull mul2(ull a, ull b) {
    ull d; asm("mul.rn.f32x2 %0, %1, %2;" : "=l"(d) : "l"(a), "l"(b)); return d;
}
__device__ __forceinline__ ull fma2(ull a, ull b, ull c) {
    ull d; asm("fma.rn.f32x2 %0, %1, %2, %3;" : "=l"(d) : "l"(a), "l"(b), "l"(c)); return d;
}
__device__ __forceinline__ void unpack2(ull v, float& lo, float& hi) {
    unsigned int l, h;
    asm("mov.b64 {%0, %1}, %2;" : "=r"(l), "=r"(h) : "l"(v));
    lo = __uint_as_float(l); hi = __uint_as_float(h);
}
__device__ __forceinline__ ull pack2(float x) {
    ull d; asm("mov.b64 %0, {%1, %1};" : "=l"(d) : "f"(x)); return d;
}

// Latency-flat sorted-insert: bd'[j]=min(max(d,bd[j-1]),bd[j]) — all levels depend
// only on OLD bd and d (no serial compare->swap chain). Exact, stable (ties keep
// earlier/lower-m element), and a no-op when d >= bd[8] so no guard is needed.
__device__ __forceinline__ void insert9(float bd[9], int bi[9], float d, int mi) {
    bool p[9];
    #pragma unroll
    for (int j = 0; j < 9; j++) p[j] = d < bd[j];
    #pragma unroll
    for (int j = 8; j >= 1; --j) bd[j] = fminf(fmaxf(d, bd[j-1]), bd[j]);
    bd[0] = fminf(d, bd[0]);
    #pragma unroll
    for (int j = 8; j >= 1; --j) bi[j] = p[j-1] ? bi[j-1] : (p[j] ? mi : bi[j]);
    bi[0] = p[0] ? mi : bi[0];
}

// cooperative transposed weight load: g[o][c] row-major -> s[c][OUT]
template<int OUT, int CIN>
__device__ __forceinline__ void load_wT(const float* __restrict__ g, float* __restrict__ s,
                                        int tid) {
    constexpr int NQ = OUT * CIN / 4;
    for (int i = tid; i < NQ; i += TPB) {
        float4 v = ((const float4*)g)[i];
        int o = i / (CIN / 4);
        int c = (i - o * (CIN / 4)) * 4;
        s[(c + 0) * OUT + o] = v.x;
        s[(c + 1) * OUT + o] = v.y;
        s[(c + 2) * OUT + o] = v.z;
        s[(c + 3) * OUT + o] = v.w;
    }
}

// 4-output x 4-n register tile; weights transposed [c][OUT]; c ascending (R2 numerics)
template<int CIN, int OUT>
__device__ __forceinline__ void gemm4x4T(const float* __restrict__ Wt,
                                         const float* __restrict__ X,
                                         int o0, int n0, float4 a[4]) {
    a[0] = make_float4(0.f, 0.f, 0.f, 0.f);
    a[1] = a[0]; a[2] = a[0]; a[3] = a[0];
    #pragma unroll 8
    for (int c = 0; c < CIN; c++) {
        float4 w = *(const float4*)&Wt[c * OUT + o0];
        float4 v = *(const float4*)&X[c * 144 + n0];
        a[0].x = fmaf(w.x, v.x, a[0].x); a[0].y = fmaf(w.x, v.y, a[0].y);
        a[0].z = fmaf(w.x, v.z, a[0].z); a[0].w = fmaf(w.x, v.w, a[0].w);
        a[1].x = fmaf(w.y, v.x, a[1].x); a[1].y = fmaf(w.y, v.y, a[1].y);
        a[1].z = fmaf(w.y, v.z, a[1].z); a[1].w = fmaf(w.y, v.w, a[1].w);
        a[2].x = fmaf(w.z, v.x, a[2].x); a[2].y = fmaf(w.z, v.y, a[2].y);
        a[2].z = fmaf(w.z, v.z, a[2].z); a[2].w = fmaf(w.z, v.w, a[2].w);
        a[3].x = fmaf(w.w, v.x, a[3].x); a[3].y = fmaf(w.w, v.y, a[3].y);
        a[3].z = fmaf(w.w, v.z, a[3].z); a[3].w = fmaf(w.w, v.w, a[3].w);
    }
}

__global__ void __launch_bounds__(TPB, 2) gcn_kernel(
    const float* __restrict__ gin,  const float* __restrict__ gpos, const float* __restrict__ grel,
    const float* __restrict__ gW1,  const float* __restrict__ gb1,
    const float* __restrict__ gWc,  const float* __restrict__ gbc,
    const float* __restrict__ gW2,  const float* __restrict__ gb2,
    const float* __restrict__ gF1,  const float* __restrict__ gfb1,
    const float* __restrict__ gF2,  const float* __restrict__ gfb2,
    float* __restrict__ gout)
{
    extern __shared__ float sm[];
    float* sW = sm;                   // 4096: W1T -> WcT -> [W2T | F1T | F2T]
    float* sB = sW + 4096;            // 192 biases
    float* sT = sB + 192;             // 4608: tmp = in+pos; later grapher output [c][n]
    float* sS = sT + 4608;            // 9216: stacked [2C][n]; later ffn hidden rows 0..31
    float* sU = sS + 9216;            // 9216: union { dist scratch | sH conv out }
    // non-overlapping dist-scratch layout (sIdx = 1296 int slots):
    float* sXn  = sU;                 // [0, 5184)      normalized nodes [n][c] stride 36
    float* sSq  = sU + 5184;          // [5184, 5328)
    int*   sIdx = (int*)(sU + 5328);  // [5328, 6624)
    float* sMrgD = sU + 6624;         // [6624, 7920)   part-1 staging dists
    int*   sMrgI = (int*)(sU + 7920); // [7920, 9216)   part-1 staging indices
    float* sH = sU;                   // conv output [64][n] (after dist scratch dead)

    const int tid = threadIdx.x;
    const int b   = blockIdx.x;
    const int q   = tid / 36;         // 0..7
    const int r   = tid - q * 36;     // 0..35
    const int n0  = r << 2;

    // ---------------- stage 0: W1T + biases + input(+pos) ----------------
    load_wT<32, 32>(gW1, sW, tid);
    if (tid < 32)       sB[tid] = gb1[tid];
    else if (tid < 96)  sB[tid] = gbc[tid - 32];
    else if (tid < 128) sB[tid] = gb2[tid - 96];
    else if (tid < 160) sB[tid] = gfb1[tid - 128];
    else if (tid < 192) sB[tid] = gfb2[tid - 160];
    {
        const float4* gi4 = (const float4*)(gin + (size_t)b * 4608);
        const float4* gp4 = (const float4*)gpos;
        for (int i = tid; i < 1152; i += TPB) {
            float4 a = gi4[i], p = gp4[i];
            a.x += p.x; a.y += p.y; a.z += p.z; a.w += p.w;
            ((float4*)sT)[i] = a;
        }
    }
    __syncthreads();

    // ---------------- fc1: xf = W1 @ tmp + b1 -> sS even rows ----------------
    {
        int o0 = q << 2;
        float4 a[4];
        gemm4x4T<32, 32>(sW, sT, o0, n0, a);
        #pragma unroll
        for (int j = 0; j < 4; j++) {
            float bb = sB[o0 + j];
            a[j].x += bb; a[j].y += bb; a[j].z += bb; a[j].w += bb;
            *(float4*)&sS[(2 * (o0 + j)) * 144 + n0] = a[j];
        }
    }
    __syncthreads();

    // ---------------- normalize (tid<144) in parallel with WcT load ----------------
    if (tid < 144) {
        float v[32]; float s = 0.f;
        #pragma unroll
        for (int c = 0; c < 32; c++) { float x = sS[(2 * c) * 144 + tid]; v[c] = x; s = fmaf(x, x, s); }
        float nrm = fmaxf(sqrtf(s), 1e-12f);
        float sq = 0.f;
        #pragma unroll
        for (int c = 0; c < 32; c++) { float xn = v[c] / nrm; sXn[tid * 36 + c] = xn; sq = fmaf(xn, xn, sq); }
        sSq[tid] = sq;
    } else {
        // WcT: 64x64 -> [c][64]
        constexpr int NQ = 64 * 64 / 4;
        for (int i = tid - 144; i < NQ; i += TPB - 144) {
            float4 v = ((const float4*)gWc)[i];
            int o = i / 16;
            int c = (i - o * 16) * 4;
            sW[(c + 0) * 64 + o] = v.x;
            sW[(c + 1) * 64 + o] = v.y;
            sW[(c + 2) * 64 + o] = v.z;
            sW[(c + 3) * 64 + o] = v.w;
        }
    }
    __syncthreads();

    // ---------------- pairwise dist + top-9 ----------------
    // part-major broadcast layout; m-loop unrolled x3 with ALL dot streams hoisted
    // ahead of the (branch-free, latency-flat) inserts -> dots cover insert latency.
    {
        const int row  = (tid < 144) ? tid : tid - 144;
        const int part = (tid < 144) ? 0 : 1;
        ull vv[16];                              // all 32 channels as 16 packed pairs
        {
            const ulonglong2* xr2 = (const ulonglong2*)&sXn[row * 36];
            #pragma unroll
            for (int i = 0; i < 8; i++) { ulonglong2 t = xr2[i]; vv[2*i] = t.x; vv[2*i+1] = t.y; }
        }
        const float sqn = sSq[row];
        float bd[9]; int bi[9];
        #pragma unroll
        for (int k = 0; k < 9; k++) { bd[k] = 3.0e38f; bi[k] = 0; }
        const int m0 = part * 72;
        const float* relp = grel + (size_t)m0 * 144 + row;
        float relv0 = relp[0];
        float relv1 = relp[144];
        float relv2 = relp[288];
        relp += 432;
        for (int mm = 0; mm < 72; mm += 3) {
            const int m = m0 + mm;
            float reln0 = 0.f, reln1 = 0.f, reln2 = 0.f;
            if (mm < 69) { reln0 = relp[0]; reln1 = relp[144]; reln2 = relp[288]; }
            relp += 432;
            const ulonglong2* xa2 = (const ulonglong2*)&sXn[m * 36];
            const ulonglong2* xb2 = xa2 + 9;
            const ulonglong2* xc2 = xa2 + 18;
            ulonglong2 t = xa2[0];
            ull a01 = mul2(vv[0], t.x);
            ull a23 = mul2(vv[1], t.y);
            ulonglong2 u = xb2[0];
            ull b01 = mul2(vv[0], u.x);
            ull b23 = mul2(vv[1], u.y);
            ulonglong2 w = xc2[0];
            ull c01 = mul2(vv[0], w.x);
            ull c23 = mul2(vv[1], w.y);
            #pragma unroll
            for (int i = 1; i < 8; i++) {
                t = xa2[i];
                a01 = fma2(vv[2*i],   t.x, a01);
                a23 = fma2(vv[2*i+1], t.y, a23);
                u = xb2[i];
                b01 = fma2(vv[2*i],   u.x, b01);
                b23 = fma2(vv[2*i+1], u.y, b23);
                w = xc2[i];
                c01 = fma2(vv[2*i],   w.x, c01);
                c23 = fma2(vv[2*i+1], w.y, c23);
            }
            float a0, a1, a2, a3, e0, e1, e2, e3, f0, f1, f2, f3;
            unpack2(a01, a0, a1); unpack2(a23, a2, a3);
            unpack2(b01, e0, e1); unpack2(b23, e2, e3);
            unpack2(c01, f0, f1); unpack2(c23, f2, f3);
            float dota = (a0 + a1) + (a2 + a3);
            float dotb = (e0 + e1) + (e2 + e3);
            float dotc = (f0 + f1) + (f2 + f3);
            float da = (sqn - 2.0f * dota) + sSq[m]     + relv0;
            float db = (sqn - 2.0f * dotb) + sSq[m + 1] + relv1;
            float dc = (sqn - 2.0f * dotc) + sSq[m + 2] + relv2;
            relv0 = reln0; relv1 = reln1; relv2 = reln2;
            // ascending m order preserves lax.top_k tie rule
            insert9(bd, bi, da, m);
            insert9(bd, bi, db, m + 1);
            insert9(bd, bi, dc, m + 2);
        }
        if (part == 1) {                          // stage part-1 lists
            int base = row * 9;
            #pragma unroll
            for (int k = 0; k < 9; k++) { sMrgD[base + k] = bd[k]; sMrgI[base + k] = bi[k]; }
        }
        __syncthreads();
        if (part == 0) {                          // merge (ascending m preserves tie rule)
            int base = row * 9;
            #pragma unroll
            for (int k = 0; k < 9; k++) {
                insert9(bd, bi, sMrgD[base + k], sMrgI[base + k]);
            }
            #pragma unroll
            for (int k = 0; k < 9; k++) sIdx[row * 9 + k] = bi[k];
        }
    }
    __syncthreads();

    // ---------------- MRConv: max over gathers, then subtract (bit-identical) ----------------
    {
        const int n2 = tid % 144;
        const int g  = tid / 144;          // 0..1 -> channels g*16..g*16+15
        int idx9[9];
        #pragma unroll
        for (int k = 0; k < 9; k++) idx9[k] = sIdx[n2 * 9 + k];
        #pragma unroll
        for (int cc = 0; cc < 16; cc++) {
            int c = g * 16 + cc;
            const float* xrow = &sS[(2 * c) * 144];
            float mx = xrow[idx9[0]];
            #pragma unroll
            for (int k = 1; k < 9; k++) mx = fmaxf(mx, xrow[idx9[k]]);
            sS[(2 * c + 1) * 144 + n2] = mx - xrow[n2];
        }
    }
    __syncthreads();

    // ---------------- hoist W2/F1/F2 LDGs (stores happen after conv barrier) ----------------
    float4 wreg[4];
    {
        #pragma unroll
        for (int k = 0; k < 4; k++) {
            int i = tid + k * TPB;
            if (i < 1024) {
                if (i < 512)      wreg[k] = ((const float4*)gW2)[i];
                else if (i < 768) wreg[k] = ((const float4*)gF1)[i - 512];
                else              wreg[k] = ((const float4*)gF2)[i - 768];
            }
        }
    }

    // ---------------- conv: hc = gelu(WcT @ stacked + bc), 8o x 4n, FFMA2-packed ----------------
    {
        const int o0 = q << 3;             // 0..56
        ull A[4][4];                       // [output-pair p][n]
        #pragma unroll
        for (int p = 0; p < 4; p++)
            #pragma unroll
            for (int n = 0; n < 4; n++) A[p][n] = 0ULL;
        #pragma unroll 4
        for (int c = 0; c < 64; c++) {
            ulonglong2 wa = *(const ulonglong2*)&sW[c * 64 + o0];      // pairs (o0,o0+1),(o0+2,o0+3)
            ulonglong2 wb = *(const ulonglong2*)&sW[c * 64 + o0 + 4];  // pairs (o0+4,o0+5),(o0+6,o0+7)
            float4 v = *(const float4*)&sS[c * 144 + n0];
            ull vd0 = pack2(v.x), vd1 = pack2(v.y), vd2 = pack2(v.z), vd3 = pack2(v.w);
            A[0][0] = fma2(wa.x, vd0, A[0][0]); A[0][1] = fma2(wa.x, vd1, A[0][1]);
            A[0][2] = fma2(wa.x, vd2, A[0][2]); A[0][3] = fma2(wa.x, vd3, A[0][3]);
            A[1][0] = fma2(wa.y, vd0, A[1][0]); A[1][1] = fma2(wa.y, vd1, A[1][1]);
            A[1][2] = fma2(wa.y, vd2, A[1][2]); A[1][3] = fma2(wa.y, vd3, A[1][3]);
            A[2][0] = fma2(wb.x, vd0, A[2][0]); A[2][1] = fma2(wb.x, vd1, A[2][1]);
            A[2][2] = fma2(wb.x, vd2, A[2][2]); A[2][3] = fma2(wb.x, vd3, A[2][3]);
            A[3][0] = fma2(wb.y, vd0, A[3][0]); A[3][1] = fma2(wb.y, vd1, A[3][1]);
            A[3][2] = fma2(wb.y, vd2, A[3][2]); A[3][3] = fma2(wb.y, vd3, A[3][3]);
        }
        #pragma unroll
        for (int p = 0; p < 4; p++) {
            float4 lo4, hi4;
            unpack2(A[p][0], lo4.x, hi4.x);
            unpack2(A[p][1], lo4.y, hi4.y);
            unpack2(A[p][2], lo4.z, hi4.z);
            unpack2(A[p][3], lo4.w, hi4.w);
            float be = sB[32 + o0 + 2 * p];
            float bo = sB[32 + o0 + 2 * p + 1];
            lo4.x = gelu_exact(lo4.x + be); lo4.y = gelu_exact(lo4.y + be);
            lo4.z = gelu_exact(lo4.z + be); lo4.w = gelu_exact(lo4.w + be);
            hi4.x = gelu_exact(hi4.x + bo); hi4.y = gelu_exact(hi4.y + bo);
            hi4.z = gelu_exact(hi4.z + bo); hi4.w = gelu_exact(hi4.w + bo);
            *(float4*)&sH[(o0 + 2 * p) * 144 + n0]     = lo4;
            *(float4*)&sH[(o0 + 2 * p + 1) * 144 + n0] = hi4;
        }
    }
    __syncthreads();

    // ---------------- scatter hoisted weights: [W2T | F1T | F2T] ----------------
    {
        #pragma unroll
        for (int k = 0; k < 4; k++) {
            int i = tid + k * TPB;
            if (i < 1024) {
                float4 v = wreg[k];
                if (i < 512) {                    // W2: OUT=32, CIN=64
                    int o = i / 16, c = (i - o * 16) * 4;
                    sW[(c + 0) * 32 + o] = v.x; sW[(c + 1) * 32 + o] = v.y;
                    sW[(c + 2) * 32 + o] = v.z; sW[(c + 3) * 32 + o] = v.w;
                } else if (i < 768) {             // F1: OUT=32, CIN=32
                    int j = i - 512, o = j / 8, c = (j - o * 8) * 4;
                    float* d = sW + 2048;
                    d[(c + 0) * 32 + o] = v.x; d[(c + 1) * 32 + o] = v.y;
                    d[(c + 2) * 32 + o] = v.z; d[(c + 3) * 32 + o] = v.w;
                } else {                          // F2: OUT=32, CIN=32
                    int j = i - 768, o = j / 8, c = (j - o * 8) * 4;
                    float* d = sW + 3072;
                    d[(c + 0) * 32 + o] = v.x; d[(c + 1) * 32 + o] = v.y;
                    d[(c + 2) * 32 + o] = v.z; d[(c + 3) * 32 + o] = v.w;
                }
            }
        }
    }
    __syncthreads();

    // ---------------- fc2 + residual -> sT (in place) ----------------
    {
        int o0 = q << 2;
        float4 a[4];
        gemm4x4T<64, 32>(sW, sH, o0, n0, a);
        #pragma unroll
        for (int j = 0; j < 4; j++) {
            float bb = sB[96 + o0 + j];
            float4 t = *(float4*)&sT[(o0 + j) * 144 + n0];
            a[j].x += bb + t.x; a[j].y += bb + t.y; a[j].z += bb + t.z; a[j].w += bb + t.w;
            *(float4*)&sT[(o0 + j) * 144 + n0] = a[j];
        }
    }
    __syncthreads();

    // ---------------- FFN fc1 -> sS rows 0..31 ----------------
    {
        int o0 = q << 2;
        float4 a[4];
        gemm4x4T<32, 32>(sW + 2048, sT, o0, n0, a);
        #pragma unroll
        for (int j = 0; j < 4; j++) {
            float bb = sB[128 + o0 + j];
            a[j].x = gelu_exact(a[j].x + bb); a[j].y = gelu_exact(a[j].y + bb);
            a[j].z = gelu_exact(a[j].z + bb); a[j].w = gelu_exact(a[j].w + bb);
            *(float4*)&sS[(o0 + j) * 144 + n0] = a[j];
        }
    }
    __syncthreads();

    // ---------------- FFN fc2 + residual -> global ----------------
    {
        int o0 = q << 2;
        float4 a[4];
        gemm4x4T<32, 32>(sW + 3072, sS, o0, n0, a);
        float* go = gout + (size_t)b * 4608;
        #pragma unroll
        for (int j = 0; j < 4; j++) {
            float bb = sB[160 + o0 + j];
            float4 t = *(float4*)&sT[(o0 + j) * 144 + n0];
            a[j].x += bb + t.x; a[j].y += bb + t.y; a[j].z += bb + t.z; a[j].w += bb + t.w;
            *(float4*)&go[(o0 + j) * 144 + n0] = a[j];
        }
    }
}

extern "C" void kernel_launch(void* const* d_in, const int* in_sizes, int n_in,
                              void* d_out, int out_size) {
    (void)n_in; (void)out_size;
    int B = in_sizes[0] / (32 * 144);
    cudaFuncSetAttribute(gcn_kernel, cudaFuncAttributeMaxDynamicSharedMemorySize, SMEM_BYTES);
    gcn_kernel<<<B, TPB, SMEM_BYTES>>>(
        (const float*)d_in[0],  (const float*)d_in[1],  (const float*)d_in[2],
        (const float*)d_in[3],  (const float*)d_in[4],
        (const float*)d_in[5],  (const float*)d_in[6],
        (const float*)d_in[7],  (const float*)d_in[8],
        (const float*)d_in[9],  (const float*)d_in[10],
        (const float*)d_in[11], (const float*)d_in[12],
        (float*)d_out);
}